// round 1
// baseline (speedup 1.0000x reference)
#include <cuda_runtime.h>
#include <cstdint>

// ---------------- problem dims ----------------
#define BB   2
#define LL   4096
#define DD   768
#define HH   12
#define HDD  64
#define NBB  64
#define MLPD 3072
#define ROWS (BB*LL)      // 8192
#define EPSV 1e-6f

// ---------------- scratch (device globals; no allocation allowed) ------------
__device__ float g_h  [ROWS*DD];
__device__ float g_q  [ROWS*DD];
__device__ float g_k  [ROWS*DD];
__device__ float g_v  [ROWS*DD];
__device__ float g_ctx[ROWS*DD];
__device__ float g_x1 [ROWS*DD];
__device__ float g_y  [ROWS*DD];
__device__ float g_z  [ROWS*MLPD];
__device__ int   g_plan[62*8];

// =====================================================================
// 1. BigBird plan: exact replica of numpy.random.RandomState(0) legacy path
// =====================================================================
struct MT19937 {
    unsigned int key[624];
    int pos;
};

__device__ void mt_seed(MT19937& s, unsigned int seed) {
    // numpy randomkit rk_seed
    for (int p = 0; p < 624; p++) {
        s.key[p] = seed;
        seed = 1812433253u * (seed ^ (seed >> 30)) + (unsigned)p + 1u;
    }
    s.pos = 624;
}

__device__ unsigned int mt_next(MT19937& s) {
    if (s.pos == 624) {
        for (int i = 0; i < 624; i++) {
            unsigned int y = (s.key[i] & 0x80000000u) | (s.key[(i + 1) % 624] & 0x7fffffffu);
            s.key[i] = s.key[(i + 397) % 624] ^ (y >> 1) ^ ((y & 1u) ? 0x9908b0dfu : 0u);
        }
        s.pos = 0;
    }
    unsigned int y = s.key[s.pos++];
    y ^= y >> 11;
    y ^= (y << 7)  & 0x9d2c5680u;
    y ^= (y << 15) & 0xefc60000u;
    y ^= y >> 18;
    return y;
}

__device__ unsigned int mt_interval(MT19937& s, unsigned int mx) {
    // numpy random_interval (masked rejection, 32-bit path)
    if (mx == 0u) return 0u;
    unsigned int mask = mx;
    mask |= mask >> 1; mask |= mask >> 2; mask |= mask >> 4;
    mask |= mask >> 8; mask |= mask >> 16;
    unsigned int v;
    while ((v = (mt_next(s) & mask)) > mx) { }
    return v;
}

__global__ void plan_kernel(int* plan) {
    MT19937 st;
    mt_seed(st, 0u);
    for (int i = 1; i <= NBB - 2; i++) {
        int cand[64]; int n = 0;
        for (int j = 0; j < NBB; j++) {
            if (j == 0 || j == NBB - 1 || j == i - 1 || j == i || j == i + 1) continue;
            cand[n++] = j;
        }
        int perm[64];
        for (int j = 0; j < n; j++) perm[j] = j;
        // numpy shuffle: for i in reversed(range(1, n)): j = interval(i); swap
        for (int ii = n - 1; ii >= 1; ii--) {
            int j = (int)mt_interval(st, (unsigned)ii);
            int t = perm[ii]; perm[ii] = perm[j]; perm[j] = t;
        }
        int* row = plan + (i - 1) * 8;
        row[0] = 0; row[1] = NBB - 1; row[2] = i - 1; row[3] = i; row[4] = i + 1;
        for (int t = 0; t < 3; t++) row[5 + t] = cand[perm[t]];
    }
}

// =====================================================================
// 2. LayerNorm: one block (256 thr) per row, D=768 = 3 elems/thread
// =====================================================================
__global__ __launch_bounds__(256) void layernorm_kernel(
    const float* __restrict__ x, const float* __restrict__ gamma,
    const float* __restrict__ beta, float* __restrict__ out)
{
    int row = blockIdx.x;
    int tid = threadIdx.x;
    const float* xr = x + (size_t)row * DD;

    float v0 = xr[tid], v1 = xr[tid + 256], v2 = xr[tid + 512];
    float s = v0 + v1 + v2;

    __shared__ float red[8];
    __shared__ float mu_s, rs_s;

    #pragma unroll
    for (int off = 16; off; off >>= 1) s += __shfl_xor_sync(0xffffffffu, s, off);
    if ((tid & 31) == 0) red[tid >> 5] = s;
    __syncthreads();
    if (tid == 0) {
        float t = 0.f;
        #pragma unroll
        for (int i = 0; i < 8; i++) t += red[i];
        mu_s = t * (1.0f / (float)DD);
    }
    __syncthreads();
    float mu = mu_s;
    float d0 = v0 - mu, d1 = v1 - mu, d2 = v2 - mu;
    float q = d0 * d0 + d1 * d1 + d2 * d2;
    #pragma unroll
    for (int off = 16; off; off >>= 1) q += __shfl_xor_sync(0xffffffffu, q, off);
    if ((tid & 31) == 0) red[tid >> 5] = q;
    __syncthreads();
    if (tid == 0) {
        float t = 0.f;
        #pragma unroll
        for (int i = 0; i < 8; i++) t += red[i];
        rs_s = rsqrtf(t * (1.0f / (float)DD) + EPSV);
    }
    __syncthreads();
    float rs = rs_s;
    float* orow = out + (size_t)row * DD;
    orow[tid]       = d0 * rs * gamma[tid]       + beta[tid];
    orow[tid + 256] = d1 * rs * gamma[tid + 256] + beta[tid + 256];
    orow[tid + 512] = d2 * rs * gamma[tid + 512] + beta[tid + 512];
}

// =====================================================================
// 3. SGEMM: C[M,N] = alpha * A[M,K] @ B[K,N]  (+bias)(relu)(+res)
//    BM=BN=128, BK=8, 256 threads, 8x8 register tile
// =====================================================================
template<bool BIAS, bool RELU, bool RES>
__global__ __launch_bounds__(256) void sgemm_kernel(
    int M, int N, int K, float alpha,
    const float* __restrict__ A, const float* __restrict__ Bm,
    const float* __restrict__ bias, const float* __restrict__ res,
    float* __restrict__ C)
{
    __shared__ float As[8][128];
    __shared__ float Bs[8][128];

    const int tid  = threadIdx.x;
    const int brow = blockIdx.y * 128;
    const int bcol = blockIdx.x * 128;
    const int tx = tid & 15, ty = tid >> 4;
    const int arow = tid >> 1,  acol = (tid & 1) * 4;
    const int brl  = tid >> 5,  bcl  = (tid & 31) * 4;

    float acc[8][8];
    #pragma unroll
    for (int i = 0; i < 8; i++)
        #pragma unroll
        for (int j = 0; j < 8; j++) acc[i][j] = 0.f;

    const float* Ag = A  + (size_t)(brow + arow) * K + acol;
    const float* Bg = Bm + (size_t)brl * N + bcol + bcl;

    for (int k0 = 0; k0 < K; k0 += 8) {
        float4 a4 = *(const float4*)(Ag + k0);
        float4 b4 = *(const float4*)(Bg + (size_t)k0 * N);
        As[acol + 0][arow] = a4.x;
        As[acol + 1][arow] = a4.y;
        As[acol + 2][arow] = a4.z;
        As[acol + 3][arow] = a4.w;
        *(float4*)&Bs[brl][bcl] = b4;
        __syncthreads();
        #pragma unroll
        for (int kk = 0; kk < 8; kk++) {
            float ra[8], rb[8];
            *(float4*)(ra)     = *(const float4*)&As[kk][ty * 8];
            *(float4*)(ra + 4) = *(const float4*)&As[kk][ty * 8 + 4];
            *(float4*)(rb)     = *(const float4*)&Bs[kk][tx * 8];
            *(float4*)(rb + 4) = *(const float4*)&Bs[kk][tx * 8 + 4];
            #pragma unroll
            for (int i = 0; i < 8; i++)
                #pragma unroll
                for (int j = 0; j < 8; j++)
                    acc[i][j] += ra[i] * rb[j];
        }
        __syncthreads();
    }

    #pragma unroll
    for (int i = 0; i < 8; i++) {
        int row = brow + ty * 8 + i;
        #pragma unroll
        for (int j = 0; j < 8; j += 4) {
            int col = bcol + tx * 8 + j;
            float4 o;
            o.x = acc[i][j + 0] * alpha;
            o.y = acc[i][j + 1] * alpha;
            o.z = acc[i][j + 2] * alpha;
            o.w = acc[i][j + 3] * alpha;
            if (BIAS) {
                o.x += bias[col + 0]; o.y += bias[col + 1];
                o.z += bias[col + 2]; o.w += bias[col + 3];
            }
            if (RELU) {
                o.x = fmaxf(o.x, 0.f); o.y = fmaxf(o.y, 0.f);
                o.z = fmaxf(o.z, 0.f); o.w = fmaxf(o.w, 0.f);
            }
            if (RES) {
                const float4 r4 = *(const float4*)&res[(size_t)row * N + col];
                o.x += r4.x; o.y += r4.y; o.z += r4.z; o.w += r4.w;
            }
            *(float4*)&C[(size_t)row * N + col] = o;
        }
    }
}

// =====================================================================
// 4. BigBird flash attention
//    grid (NB=64, H=12, B=2), 128 threads (4 warps).
//    warp w owns query rows r = w + 4*i (i=0..15); lane = key-chunk column.
//    32-key chunks; online softmax in registers; P staged via smem.
// =====================================================================
__global__ __launch_bounds__(128) void attn_kernel(
    const float* __restrict__ q, const float* __restrict__ k,
    const float* __restrict__ v, const int* __restrict__ plan,
    float* __restrict__ ctx)
{
    __shared__ float Qs[64 * 64];   // 16 KB
    __shared__ float Ks[32 * 68];   // padded: conflict-free lane-major reads
    __shared__ float Vs[32 * 64];
    __shared__ float Ps[64 * 33];   // padded P stage

    const int qb = blockIdx.x, h = blockIdx.y, b = blockIdx.z;
    const int tid = threadIdx.x;
    const int w = tid >> 5, lane = tid & 31;

    // load Q tile (already pre-scaled by 1/sqrt(HD) in the q GEMM)
    const size_t qbase = ((size_t)(b * LL + qb * 64)) * DD + h * HDD;
    #pragma unroll
    for (int i = 0; i < 8; i++) {
        int f = tid + i * 128;        // 1024 float4s total
        int r = f >> 4, d4 = (f & 15) * 4;
        *(float4*)&Qs[r * 64 + d4] = *(const float4*)&q[qbase + (size_t)r * DD + d4];
    }

    float mreg[16], lreg[16], o0[16], o1[16];
    #pragma unroll
    for (int i = 0; i < 16; i++) { mreg[i] = -1e30f; lreg[i] = 0.f; o0[i] = 0.f; o1[i] = 0.f; }

    const int nkb = (qb == 0 || qb == NBB - 1) ? NBB : 8;

    for (int kbi = 0; kbi < nkb; kbi++) {
        int kb = (nkb == NBB) ? kbi : plan[(qb - 1) * 8 + kbi];
        for (int half = 0; half < 2; half++) {
            __syncthreads();   // protect Ks/Vs (and first-iter Qs) from prior consumers
            const size_t kbase = ((size_t)(b * LL + kb * 64 + half * 32)) * DD + h * HDD;
            #pragma unroll
            for (int i = 0; i < 4; i++) {
                int f = tid + i * 128;    // 512 float4s
                int c = f >> 4, d4 = (f & 15) * 4;
                *(float4*)&Ks[c * 68 + d4] = *(const float4*)&k[kbase + (size_t)c * DD + d4];
                *(float4*)&Vs[c * 64 + d4] = *(const float4*)&v[kbase + (size_t)c * DD + d4];
            }
            __syncthreads();

            // ---- QK^T + online softmax, one row at a time per warp ----
            #pragma unroll
            for (int i = 0; i < 16; i++) {
                int r = w + i * 4;
                const float4* qr = (const float4*)&Qs[r * 64];
                const float4* kr = (const float4*)&Ks[lane * 68];
                float s = 0.f;
                #pragma unroll
                for (int d4 = 0; d4 < 16; d4++) {
                    float4 a = qr[d4]; float4 bb = kr[d4];
                    s += a.x * bb.x + a.y * bb.y + a.z * bb.z + a.w * bb.w;
                }
                float cm = s;
                #pragma unroll
                for (int off = 16; off; off >>= 1)
                    cm = fmaxf(cm, __shfl_xor_sync(0xffffffffu, cm, off));
                float mn = fmaxf(mreg[i], cm);
                float sc = __expf(mreg[i] - mn);
                float p  = __expf(s - mn);
                float ps = p;
                #pragma unroll
                for (int off = 16; off; off >>= 1)
                    ps += __shfl_xor_sync(0xffffffffu, ps, off);
                lreg[i] = lreg[i] * sc + ps;
                mreg[i] = mn;
                o0[i] *= sc; o1[i] *= sc;
                Ps[r * 33 + lane] = p;
            }
            __syncwarp();

            // ---- P @ V: lane owns output dims (lane, lane+32), 2 rows at a time ----
            #pragma unroll
            for (int i = 0; i < 16; i += 2) {
                int r0 = w + i * 4, r1 = r0 + 4;
                float a0 = o0[i], a1 = o1[i], b0 = o0[i + 1], b1 = o1[i + 1];
                #pragma unroll
                for (int c = 0; c < 32; c++) {
                    float vv0 = Vs[c * 64 + lane];
                    float vv1 = Vs[c * 64 + lane + 32];
                    float p0 = Ps[r0 * 33 + c];
                    float p1 = Ps[r1 * 33 + c];
                    a0 += p0 * vv0; a1 += p0 * vv1;
                    b0 += p1 * vv0; b1 += p1 * vv1;
                }
                o0[i] = a0; o1[i] = a1; o0[i + 1] = b0; o1[i + 1] = b1;
            }
        }
    }

    // write context in [B*L, D] layout (col = h*64 + d) for the Wo GEMM
    const size_t obase = ((size_t)(b * LL + qb * 64)) * DD + h * HDD;
    #pragma unroll
    for (int i = 0; i < 16; i++) {
        int r = w + i * 4;
        float inv = 1.0f / lreg[i];
        ctx[obase + (size_t)r * DD + lane]      = o0[i] * inv;
        ctx[obase + (size_t)r * DD + lane + 32] = o1[i] * inv;
    }
}

// =====================================================================
// launch
// =====================================================================
extern "C" void kernel_launch(void* const* d_in, const int* in_sizes, int n_in,
                              void* d_out, int out_size)
{
    (void)in_sizes; (void)n_in; (void)out_size;
    const float* x    = (const float*)d_in[0];
    const float* ln1s = (const float*)d_in[1];
    const float* ln1b = (const float*)d_in[2];
    const float* Wq   = (const float*)d_in[3];   // [D, H*HD] flat
    const float* Wk   = (const float*)d_in[4];
    const float* Wv   = (const float*)d_in[5];
    const float* Wo   = (const float*)d_in[6];   // [H*HD, D] flat
    const float* ln2s = (const float*)d_in[7];
    const float* ln2b = (const float*)d_in[8];
    const float* W1   = (const float*)d_in[9];   // [D, MLP]
    const float* b1   = (const float*)d_in[10];
    const float* W2   = (const float*)d_in[11];  // [MLP, D]
    const float* b2   = (const float*)d_in[12];
    float* out = (float*)d_out;

    void *ph, *pq, *pk, *pv, *pctx, *px1, *py, *pz, *pplan;
    cudaGetSymbolAddress(&ph,   g_h);
    cudaGetSymbolAddress(&pq,   g_q);
    cudaGetSymbolAddress(&pk,   g_k);
    cudaGetSymbolAddress(&pv,   g_v);
    cudaGetSymbolAddress(&pctx, g_ctx);
    cudaGetSymbolAddress(&px1,  g_x1);
    cudaGetSymbolAddress(&py,   g_y);
    cudaGetSymbolAddress(&pz,   g_z);
    cudaGetSymbolAddress(&pplan, g_plan);

    float* fh   = (float*)ph;
    float* fq   = (float*)pq;
    float* fk   = (float*)pk;
    float* fv   = (float*)pv;
    float* fctx = (float*)pctx;
    float* fx1  = (float*)px1;
    float* fy   = (float*)py;
    float* fz   = (float*)pz;
    int*   fplan = (int*)pplan;

    // 0) static BigBird plan (exact numpy MT19937 replica)
    plan_kernel<<<1, 1>>>(fplan);

    // 1) h = LN1(x)
    layernorm_kernel<<<ROWS, 256>>>(x, ln1s, ln1b, fh);

    // 2) q = 0.125 * h@Wq ; k = h@Wk ; v = h@Wv
    dim3 gqkv(DD / 128, ROWS / 128);
    sgemm_kernel<false, false, false><<<gqkv, 256>>>(ROWS, DD, DD, 0.125f, fh, Wq, nullptr, nullptr, fq);
    sgemm_kernel<false, false, false><<<gqkv, 256>>>(ROWS, DD, DD, 1.0f,   fh, Wk, nullptr, nullptr, fk);
    sgemm_kernel<false, false, false><<<gqkv, 256>>>(ROWS, DD, DD, 1.0f,   fh, Wv, nullptr, nullptr, fv);

    // 3) BigBird attention -> ctx [B*L, D]
    attn_kernel<<<dim3(NBB, HH, BB), 128>>>(fq, fk, fv, fplan, fctx);

    // 4) x1 = ctx @ Wo + x
    sgemm_kernel<false, false, true><<<gqkv, 256>>>(ROWS, DD, DD, 1.0f, fctx, Wo, nullptr, x, fx1);

    // 5) y = LN2(x1)
    layernorm_kernel<<<ROWS, 256>>>(fx1, ln2s, ln2b, fy);

    // 6) z = relu(y @ W1 + b1)
    dim3 gm1(MLPD / 128, ROWS / 128);
    sgemm_kernel<true, true, false><<<gm1, 256>>>(ROWS, MLPD, DD, 1.0f, fy, W1, b1, nullptr, fz);

    // 7) out = z @ W2 + b2 + x1
    sgemm_kernel<true, false, true><<<gqkv, 256>>>(ROWS, DD, MLPD, 1.0f, fz, W2, b2, fx1, out);
}

// round 3
// speedup vs baseline: 2.0721x; 2.0721x over previous
#include <cuda_runtime.h>
#include <cstdint>

// ---------------- problem dims ----------------
#define BB   2
#define LL   4096
#define DD   768
#define HH   12
#define HDD  64
#define NBB  64
#define MLPD 3072
#define ROWS (BB*LL)      // 8192
#define EPSV 1e-6f

// ---------------- scratch (device globals; no allocation allowed) ------------
__device__ float g_h  [ROWS*DD];
__device__ float g_q  [ROWS*DD];
__device__ float g_k  [ROWS*DD];
__device__ float g_v  [ROWS*DD];
__device__ float g_ctx[ROWS*DD];
__device__ float g_x1 [ROWS*DD];
__device__ float g_y  [ROWS*DD];
__device__ float g_z  [ROWS*MLPD];
// transposed (K-major) weights
__device__ float g_wqt[DD*DD];
__device__ float g_wkt[DD*DD];
__device__ float g_wvt[DD*DD];
__device__ float g_wot[DD*DD];
__device__ float g_w1t[MLPD*DD];
__device__ float g_w2t[DD*MLPD];

// =====================================================================
// helpers
// =====================================================================
__device__ __forceinline__ uint32_t f2tf32(float x) {
    uint32_t r;
    asm("cvt.rna.tf32.f32 %0, %1;" : "=r"(r) : "f"(x));
    return r;
}

__device__ __forceinline__ void mma8(float* d, const uint32_t* a, const uint32_t* b) {
    asm volatile(
        "mma.sync.aligned.m16n8k8.row.col.f32.tf32.tf32.f32 "
        "{%0,%1,%2,%3}, {%4,%5,%6,%7}, {%8,%9}, {%0,%1,%2,%3};"
        : "+f"(d[0]), "+f"(d[1]), "+f"(d[2]), "+f"(d[3])
        : "r"(a[0]), "r"(a[1]), "r"(a[2]), "r"(a[3]), "r"(b[0]), "r"(b[1]));
}

// =====================================================================
// transpose: out[C,R] = in[R,C]^T   (R,C multiples of 32)
// =====================================================================
__global__ __launch_bounds__(256) void transpose_kernel(
    const float* __restrict__ in, float* __restrict__ out, int R, int C)
{
    __shared__ float t[32][33];
    int c0 = blockIdx.x * 32, r0 = blockIdx.y * 32;
    int x = threadIdx.x, y = threadIdx.y;
    #pragma unroll
    for (int i = 0; i < 32; i += 8)
        t[y + i][x] = in[(size_t)(r0 + y + i) * C + c0 + x];
    __syncthreads();
    #pragma unroll
    for (int i = 0; i < 32; i += 8)
        out[(size_t)(c0 + y + i) * R + r0 + x] = t[x][y + i];
}

// =====================================================================
// LayerNorm: one block (256 thr) per row, D=768 = 3 elems/thread
// =====================================================================
__global__ __launch_bounds__(256) void layernorm_kernel(
    const float* __restrict__ x, const float* __restrict__ gamma,
    const float* __restrict__ beta, float* __restrict__ out)
{
    int row = blockIdx.x;
    int tid = threadIdx.x;
    const float* xr = x + (size_t)row * DD;

    float v0 = xr[tid], v1 = xr[tid + 256], v2 = xr[tid + 512];
    float s = v0 + v1 + v2;

    __shared__ float red[8];
    __shared__ float mu_s, rs_s;

    #pragma unroll
    for (int off = 16; off; off >>= 1) s += __shfl_xor_sync(0xffffffffu, s, off);
    if ((tid & 31) == 0) red[tid >> 5] = s;
    __syncthreads();
    if (tid == 0) {
        float t = 0.f;
        #pragma unroll
        for (int i = 0; i < 8; i++) t += red[i];
        mu_s = t * (1.0f / (float)DD);
    }
    __syncthreads();
    float mu = mu_s;
    float d0 = v0 - mu, d1 = v1 - mu, d2 = v2 - mu;
    float q = d0 * d0 + d1 * d1 + d2 * d2;
    #pragma unroll
    for (int off = 16; off; off >>= 1) q += __shfl_xor_sync(0xffffffffu, q, off);
    if ((tid & 31) == 0) red[tid >> 5] = q;
    __syncthreads();
    if (tid == 0) {
        float t = 0.f;
        #pragma unroll
        for (int i = 0; i < 8; i++) t += red[i];
        rs_s = rsqrtf(t * (1.0f / (float)DD) + EPSV);
    }
    __syncthreads();
    float rs = rs_s;
    float* orow = out + (size_t)row * DD;
    orow[tid]       = d0 * rs * gamma[tid]       + beta[tid];
    orow[tid + 256] = d1 * rs * gamma[tid + 256] + beta[tid + 256];
    orow[tid + 512] = d2 * rs * gamma[tid + 512] + beta[tid + 512];
}

// =====================================================================
// mma.sync tf32 GEMM: C[M,N] = alpha*A[M,K]@B + bias + relu + res
//   A: [M,K] row-major fp32 ; Bt: [N,K] row-major fp32 (pre-transposed)
//   block 128x128, K chunks of 32, 8 warps (2x4) of 64x32 warp tiles,
//   m16n8k8 tf32 mma, fragment-native smem with rotation swizzle
//   (conflict-free STS.128 stores AND LDS.32 fragment loads).
// =====================================================================
template<bool BIAS, bool RELU, bool RES>
__global__ __launch_bounds__(256) void mma_gemm(
    int M, int N, int K, float alpha,
    const float* __restrict__ A, const float* __restrict__ Bt,
    const float* __restrict__ bias, const float* __restrict__ res,
    float* __restrict__ C)
{
    __shared__ uint32_t As[4096];   // ((mt*4+ks)*4+reg)*32 + rot(lane) : 16KB
    __shared__ uint32_t Bs[4096];   // ((nt*4+ks)*2+reg)*32 + rot(lane) : 16KB

    const int tid  = threadIdx.x;
    const int lane = tid & 31, wid = tid >> 5;
    const int g = lane >> 2, t4 = lane & 3;
    const int wm = wid & 1, wn = wid >> 1;       // warp grid 2 (m) x 4 (n)
    const int brow = blockIdx.y * 128;
    const int bcol = blockIdx.x * 128;

    // ---- per-i gmem/smem store geometry (i = 0..3, f = tid + 256*i) ----
    int rowi[4], smA[4], smB[4], kofs[4];
    #pragma unroll
    for (int i = 0; i < 4; i++) {
        int f = tid + i * 256;
        int r = f >> 3, j = f & 7;           // r: tile row 0..127, j: k-group 0..7
        int ks = j >> 1, chi = j & 1;
        rowi[i] = r;
        kofs[i] = j * 4;
        int mt = r >> 4, hi = (r >> 3) & 1, gg = r & 7;
        int slot = (gg * 4 + 8 * ks + 4 * chi) & 31;     // rotation swizzle
        smA[i] = ((mt * 4 + ks) * 4 + (hi + 2 * chi)) * 32 + slot;
        int nt = r >> 3;                                  // B row index 0..127 -> nt 0..15
        smB[i] = ((nt * 4 + ks) * 2 + chi) * 32 + (((r & 7) * 4 + 8 * ks + 4 * chi) & 31);
    }

    float acc[4][4][4];
    #pragma unroll
    for (int mt = 0; mt < 4; mt++)
        #pragma unroll
        for (int nt = 0; nt < 4; nt++)
            #pragma unroll
            for (int r = 0; r < 4; r++) acc[mt][nt][r] = 0.f;

    const int nc = K >> 5;
    float4 va[4], vb[4];

    // prologue: chunk 0
    #pragma unroll
    for (int i = 0; i < 4; i++) {
        va[i] = *(const float4*)&A [(size_t)(brow + rowi[i]) * K + kofs[i]];
        vb[i] = *(const float4*)&Bt[(size_t)(bcol + rowi[i]) * K + kofs[i]];
    }
    #pragma unroll
    for (int i = 0; i < 4; i++) {
        uint4 ua; ua.x = f2tf32(va[i].x); ua.y = f2tf32(va[i].y); ua.z = f2tf32(va[i].z); ua.w = f2tf32(va[i].w);
        *(uint4*)&As[smA[i]] = ua;
        uint4 ub; ub.x = f2tf32(vb[i].x); ub.y = f2tf32(vb[i].y); ub.z = f2tf32(vb[i].z); ub.w = f2tf32(vb[i].w);
        *(uint4*)&Bs[smB[i]] = ub;
    }
    __syncthreads();

    for (int ch = 0; ch < nc; ch++) {
        const bool more = (ch + 1 < nc);
        if (more) {
            const int k0 = (ch + 1) << 5;
            #pragma unroll
            for (int i = 0; i < 4; i++) {
                va[i] = *(const float4*)&A [(size_t)(brow + rowi[i]) * K + k0 + kofs[i]];
                vb[i] = *(const float4*)&Bt[(size_t)(bcol + rowi[i]) * K + k0 + kofs[i]];
            }
        }

        // ---- MMA over the 32-K chunk ----
        #pragma unroll
        for (int ks = 0; ks < 4; ks++) {
            uint32_t af[4][4], bf[4][2];
            #pragma unroll
            for (int mt = 0; mt < 4; mt++) {
                const int mtg = wm * 4 + mt;
                #pragma unroll
                for (int r = 0; r < 4; r++) {
                    int slot = (lane + 8 * ks + 4 * (r >> 1)) & 31;
                    af[mt][r] = As[((mtg * 4 + ks) * 4 + r) * 32 + slot];
                }
            }
            #pragma unroll
            for (int nt = 0; nt < 4; nt++) {
                const int ntg = wn * 4 + nt;
                #pragma unroll
                for (int r = 0; r < 2; r++) {
                    int slot = (lane + 8 * ks + 4 * r) & 31;
                    bf[nt][r] = Bs[((ntg * 4 + ks) * 2 + r) * 32 + slot];
                }
            }
            #pragma unroll
            for (int mt = 0; mt < 4; mt++)
                #pragma unroll
                for (int nt = 0; nt < 4; nt++)
                    mma8(acc[mt][nt], af[mt], bf[nt]);
        }
        __syncthreads();

        if (more) {
            #pragma unroll
            for (int i = 0; i < 4; i++) {
                uint4 ua; ua.x = f2tf32(va[i].x); ua.y = f2tf32(va[i].y); ua.z = f2tf32(va[i].z); ua.w = f2tf32(va[i].w);
                *(uint4*)&As[smA[i]] = ua;
                uint4 ub; ub.x = f2tf32(vb[i].x); ub.y = f2tf32(vb[i].y); ub.z = f2tf32(vb[i].z); ub.w = f2tf32(vb[i].w);
                *(uint4*)&Bs[smB[i]] = ub;
            }
            __syncthreads();
        }
    }

    // ---- epilogue ----
    #pragma unroll
    for (int mt = 0; mt < 4; mt++) {
        const int row0 = brow + wm * 64 + mt * 16 + g;
        const int row1 = row0 + 8;
        #pragma unroll
        for (int nt = 0; nt < 4; nt++) {
            const int col = bcol + wn * 32 + nt * 8 + t4 * 2;
            float2 lo, hi;
            lo.x = acc[mt][nt][0] * alpha; lo.y = acc[mt][nt][1] * alpha;
            hi.x = acc[mt][nt][2] * alpha; hi.y = acc[mt][nt][3] * alpha;
            if (BIAS) {
                const float2 bb = *(const float2*)&bias[col];
                lo.x += bb.x; lo.y += bb.y; hi.x += bb.x; hi.y += bb.y;
            }
            if (RELU) {
                lo.x = fmaxf(lo.x, 0.f); lo.y = fmaxf(lo.y, 0.f);
                hi.x = fmaxf(hi.x, 0.f); hi.y = fmaxf(hi.y, 0.f);
            }
            if (RES) {
                const float2 r0 = *(const float2*)&res[(size_t)row0 * N + col];
                const float2 r1 = *(const float2*)&res[(size_t)row1 * N + col];
                lo.x += r0.x; lo.y += r0.y; hi.x += r1.x; hi.y += r1.y;
            }
            *(float2*)&C[(size_t)row0 * N + col] = lo;
            *(float2*)&C[(size_t)row1 * N + col] = hi;
        }
    }
}

// =====================================================================
// BigBird flash attention
//   grid (NB=64, H=12, B=2), 256 threads (8 warps), warp w owns rows w+8i.
//   Plan passed as by-value kernel parameter (constant bank).
// =====================================================================
struct PlanT { int v[(NBB - 2) * 8]; };

__global__ __launch_bounds__(256) void attn_kernel(
    const float* __restrict__ q, const float* __restrict__ k,
    const float* __restrict__ v, const PlanT plan,
    float* __restrict__ ctx)
{
    __shared__ float Qs[64 * 64];   // 16 KB
    __shared__ float Ks[32 * 68];   // padded: conflict-free lane-major reads
    __shared__ float Vs[32 * 64];
    __shared__ float Ps[64 * 33];   // padded P stage

    const int qb = blockIdx.x, h = blockIdx.y, b = blockIdx.z;
    const int tid = threadIdx.x;
    const int w = tid >> 5, lane = tid & 31;

    // load Q tile (pre-scaled by 1/sqrt(HD) in the q GEMM)
    const size_t qbase = ((size_t)(b * LL + qb * 64)) * DD + h * HDD;
    #pragma unroll
    for (int i = 0; i < 4; i++) {
        int f = tid + i * 256;        // 1024 float4s total
        int r = f >> 4, d4 = (f & 15) * 4;
        *(float4*)&Qs[r * 64 + d4] = *(const float4*)&q[qbase + (size_t)r * DD + d4];
    }

    float mreg[8], lreg[8], o0[8], o1[8];
    #pragma unroll
    for (int i = 0; i < 8; i++) { mreg[i] = -1e30f; lreg[i] = 0.f; o0[i] = 0.f; o1[i] = 0.f; }

    const int nkb = (qb == 0 || qb == NBB - 1) ? NBB : 8;

    for (int kbi = 0; kbi < nkb; kbi++) {
        int kb = (nkb == NBB) ? kbi : plan.v[(qb - 1) * 8 + kbi];
        for (int half = 0; half < 2; half++) {
            __syncthreads();   // protect Ks/Vs (and first-iter Qs) from prior consumers
            const size_t kbase = ((size_t)(b * LL + kb * 64 + half * 32)) * DD + h * HDD;
            #pragma unroll
            for (int i = 0; i < 2; i++) {
                int f = tid + i * 256;    // 512 float4s
                int c = f >> 4, d4 = (f & 15) * 4;
                *(float4*)&Ks[c * 68 + d4] = *(const float4*)&k[kbase + (size_t)c * DD + d4];
                *(float4*)&Vs[c * 64 + d4] = *(const float4*)&v[kbase + (size_t)c * DD + d4];
            }
            __syncthreads();

            // ---- QK^T + online softmax, one row at a time per warp ----
            #pragma unroll
            for (int i = 0; i < 8; i++) {
                int r = w + i * 8;
                const float4* qr = (const float4*)&Qs[r * 64];
                const float4* kr = (const float4*)&Ks[lane * 68];
                float s = 0.f;
                #pragma unroll
                for (int d4 = 0; d4 < 16; d4++) {
                    float4 a = qr[d4]; float4 bb = kr[d4];
                    s += a.x * bb.x + a.y * bb.y + a.z * bb.z + a.w * bb.w;
                }
                float cm = s;
                #pragma unroll
                for (int off = 16; off; off >>= 1)
                    cm = fmaxf(cm, __shfl_xor_sync(0xffffffffu, cm, off));
                float mn = fmaxf(mreg[i], cm);
                float sc = __expf(mreg[i] - mn);
                float p  = __expf(s - mn);
                float ps = p;
                #pragma unroll
                for (int off = 16; off; off >>= 1)
                    ps += __shfl_xor_sync(0xffffffffu, ps, off);
                lreg[i] = lreg[i] * sc + ps;
                mreg[i] = mn;
                o0[i] *= sc; o1[i] *= sc;
                Ps[r * 33 + lane] = p;
            }
            __syncwarp();

            // ---- P @ V: lane owns output dims (lane, lane+32), 2 rows at a time ----
            #pragma unroll
            for (int i = 0; i < 8; i += 2) {
                int r0 = w + i * 8, r1 = r0 + 8;
                float a0 = o0[i], a1 = o1[i], b0 = o0[i + 1], b1 = o1[i + 1];
                #pragma unroll
                for (int c = 0; c < 32; c++) {
                    float vv0 = Vs[c * 64 + lane];
                    float vv1 = Vs[c * 64 + lane + 32];
                    float p0 = Ps[r0 * 33 + c];
                    float p1 = Ps[r1 * 33 + c];
                    a0 += p0 * vv0; a1 += p0 * vv1;
                    b0 += p1 * vv0; b1 += p1 * vv1;
                }
                o0[i] = a0; o1[i] = a1; o0[i + 1] = b0; o1[i + 1] = b1;
            }
        }
    }

    // write context in [B*L, D] layout (col = h*64 + d) for the Wo GEMM
    const size_t obase = ((size_t)(b * LL + qb * 64)) * DD + h * HDD;
    #pragma unroll
    for (int i = 0; i < 8; i++) {
        int r = w + i * 8;
        float inv = 1.0f / lreg[i];
        ctx[obase + (size_t)r * DD + lane]      = o0[i] * inv;
        ctx[obase + (size_t)r * DD + lane + 32] = o1[i] * inv;
    }
}

// =====================================================================
// host-side numpy MT19937 (legacy RandomState(0)) -> BigBird plan
// =====================================================================
namespace hostmt {
struct MT {
    unsigned int key[624];
    int pos;
};
static void mt_seed(MT& s, unsigned int seed) {
    for (int p = 0; p < 624; p++) {
        s.key[p] = seed;
        seed = 1812433253u * (seed ^ (seed >> 30)) + (unsigned)p + 1u;
    }
    s.pos = 624;
}
static unsigned int mt_next(MT& s) {
    if (s.pos == 624) {
        for (int i = 0; i < 624; i++) {
            unsigned int y = (s.key[i] & 0x80000000u) | (s.key[(i + 1) % 624] & 0x7fffffffu);
            s.key[i] = s.key[(i + 397) % 624] ^ (y >> 1) ^ ((y & 1u) ? 0x9908b0dfu : 0u);
        }
        s.pos = 0;
    }
    unsigned int y = s.key[s.pos++];
    y ^= y >> 11;
    y ^= (y << 7)  & 0x9d2c5680u;
    y ^= (y << 15) & 0xefc60000u;
    y ^= y >> 18;
    return y;
}
static unsigned int mt_interval(MT& s, unsigned int mx) {
    if (mx == 0u) return 0u;
    unsigned int mask = mx;
    mask |= mask >> 1; mask |= mask >> 2; mask |= mask >> 4;
    mask |= mask >> 8; mask |= mask >> 16;
    unsigned int v;
    while ((v = (mt_next(s) & mask)) > mx) { }
    return v;
}
static void make_plan(int* plan) {
    MT st;
    mt_seed(st, 0u);
    for (int i = 1; i <= NBB - 2; i++) {
        int cand[64]; int n = 0;
        for (int j = 0; j < NBB; j++) {
            if (j == 0 || j == NBB - 1 || j == i - 1 || j == i || j == i + 1) continue;
            cand[n++] = j;
        }
        int perm[64];
        for (int j = 0; j < n; j++) perm[j] = j;
        for (int ii = n - 1; ii >= 1; ii--) {
            int j = (int)mt_interval(st, (unsigned)ii);
            int t = perm[ii]; perm[ii] = perm[j]; perm[j] = t;
        }
        int* row = plan + (i - 1) * 8;
        row[0] = 0; row[1] = NBB - 1; row[2] = i - 1; row[3] = i; row[4] = i + 1;
        for (int t = 0; t < 3; t++) row[5 + t] = cand[perm[t]];
    }
}
} // namespace hostmt

// =====================================================================
// launch
// =====================================================================
extern "C" void kernel_launch(void* const* d_in, const int* in_sizes, int n_in,
                              void* d_out, int out_size)
{
    (void)in_sizes; (void)n_in; (void)out_size;
    const float* x    = (const float*)d_in[0];
    const float* ln1s = (const float*)d_in[1];
    const float* ln1b = (const float*)d_in[2];
    const float* Wq   = (const float*)d_in[3];   // [D, H*HD] flat
    const float* Wk   = (const float*)d_in[4];
    const float* Wv   = (const float*)d_in[5];
    const float* Wo   = (const float*)d_in[6];   // [H*HD, D] flat
    const float* ln2s = (const float*)d_in[7];
    const float* ln2b = (const float*)d_in[8];
    const float* W1   = (const float*)d_in[9];   // [D, MLP]
    const float* b1   = (const float*)d_in[10];
    const float* W2   = (const float*)d_in[11];  // [MLP, D]
    const float* b2   = (const float*)d_in[12];
    float* out = (float*)d_out;

    void *ph, *pq, *pk, *pv, *pctx, *px1, *py, *pz;
    void *pwqt, *pwkt, *pwvt, *pwot, *pw1t, *pw2t;
    cudaGetSymbolAddress(&ph,   g_h);
    cudaGetSymbolAddress(&pq,   g_q);
    cudaGetSymbolAddress(&pk,   g_k);
    cudaGetSymbolAddress(&pv,   g_v);
    cudaGetSymbolAddress(&pctx, g_ctx);
    cudaGetSymbolAddress(&px1,  g_x1);
    cudaGetSymbolAddress(&py,   g_y);
    cudaGetSymbolAddress(&pz,   g_z);
    cudaGetSymbolAddress(&pwqt, g_wqt);
    cudaGetSymbolAddress(&pwkt, g_wkt);
    cudaGetSymbolAddress(&pwvt, g_wvt);
    cudaGetSymbolAddress(&pwot, g_wot);
    cudaGetSymbolAddress(&pw1t, g_w1t);
    cudaGetSymbolAddress(&pw2t, g_w2t);

    float* fh   = (float*)ph;
    float* fq   = (float*)pq;
    float* fk   = (float*)pk;
    float* fv   = (float*)pv;
    float* fctx = (float*)pctx;
    float* fx1  = (float*)px1;
    float* fy   = (float*)py;
    float* fz   = (float*)pz;
    float* wqt  = (float*)pwqt;
    float* wkt  = (float*)pwkt;
    float* wvt  = (float*)pwvt;
    float* wot  = (float*)pwot;
    float* w1t  = (float*)pw1t;
    float* w2t  = (float*)pw2t;

    // host-computed BigBird plan (numpy MT19937 replica) as kernel param
    PlanT plan;
    hostmt::make_plan(plan.v);

    dim3 tb(32, 8);

    // 0) weight transposes -> K-major [N,K]
    transpose_kernel<<<dim3(DD / 32, DD / 32), tb>>>(Wq, wqt, DD, DD);
    transpose_kernel<<<dim3(DD / 32, DD / 32), tb>>>(Wk, wkt, DD, DD);
    transpose_kernel<<<dim3(DD / 32, DD / 32), tb>>>(Wv, wvt, DD, DD);
    transpose_kernel<<<dim3(DD / 32, DD / 32), tb>>>(Wo, wot, DD, DD);
    transpose_kernel<<<dim3(MLPD / 32, DD / 32), tb>>>(W1, w1t, DD, MLPD);
    transpose_kernel<<<dim3(DD / 32, MLPD / 32), tb>>>(W2, w2t, MLPD, DD);

    // 1) h = LN1(x)
    layernorm_kernel<<<ROWS, 256>>>(x, ln1s, ln1b, fh);

    // 2) q = 0.125 * h@Wq ; k = h@Wk ; v = h@Wv
    dim3 gqkv(DD / 128, ROWS / 128);
    mma_gemm<false, false, false><<<gqkv, 256>>>(ROWS, DD, DD, 0.125f, fh, wqt, nullptr, nullptr, fq);
    mma_gemm<false, false, false><<<gqkv, 256>>>(ROWS, DD, DD, 1.0f,   fh, wkt, nullptr, nullptr, fk);
    mma_gemm<false, false, false><<<gqkv, 256>>>(ROWS, DD, DD, 1.0f,   fh, wvt, nullptr, nullptr, fv);

    // 3) BigBird attention -> ctx [B*L, D]
    attn_kernel<<<dim3(NBB, HH, BB), 256>>>(fq, fk, fv, plan, fctx);

    // 4) x1 = ctx @ Wo + x
    mma_gemm<false, false, true><<<gqkv, 256>>>(ROWS, DD, DD, 1.0f, fctx, wot, nullptr, x, fx1);

    // 5) y = LN2(x1)
    layernorm_kernel<<<ROWS, 256>>>(fx1, ln2s, ln2b, fy);

    // 6) z = relu(y @ W1 + b1)
    dim3 gm1(MLPD / 128, ROWS / 128);
    mma_gemm<true, true, false><<<gm1, 256>>>(ROWS, MLPD, DD, 1.0f, fy, w1t, b1, nullptr, fz);

    // 7) out = z @ W2 + b2 + x1
    mma_gemm<true, false, true><<<gqkv, 256>>>(ROWS, DD, MLPD, 1.0f, fz, w2t, b2, fx1, out);
}

// round 4
// speedup vs baseline: 2.3260x; 1.1225x over previous
#include <cuda_runtime.h>
#include <cstdint>

// ---------------- problem dims ----------------
#define BB   2
#define LL   4096
#define DD   768
#define HH   12
#define HDD  64
#define NBB  64
#define MLPD 3072
#define ROWS (BB*LL)      // 8192
#define QKVD (3*DD)       // 2304
#define EPSV 1e-6f

// ---------------- scratch (device globals; no allocation allowed) ------------
__device__ float g_h  [ROWS*DD];
__device__ float g_qkv[ROWS*QKVD];
__device__ float g_ctx[ROWS*DD];
__device__ float g_x1 [ROWS*DD];
__device__ float g_y  [ROWS*DD];
__device__ float g_z  [ROWS*MLPD];
// transposed (K-major) weights
__device__ float g_wqkvt[QKVD*DD];   // rows: [Wq^T ; Wk^T ; Wv^T]
__device__ float g_wot[DD*DD];
__device__ float g_w1t[MLPD*DD];
__device__ float g_w2t[DD*MLPD];

// =====================================================================
// helpers
// =====================================================================
__device__ __forceinline__ uint32_t f2tf32(float x) {
    uint32_t r;
    asm("cvt.rna.tf32.f32 %0, %1;" : "=r"(r) : "f"(x));
    return r;
}

__device__ __forceinline__ void mma8(float* d, const uint32_t* a, const uint32_t* b) {
    asm volatile(
        "mma.sync.aligned.m16n8k8.row.col.f32.tf32.tf32.f32 "
        "{%0,%1,%2,%3}, {%4,%5,%6,%7}, {%8,%9}, {%0,%1,%2,%3};"
        : "+f"(d[0]), "+f"(d[1]), "+f"(d[2]), "+f"(d[3])
        : "r"(a[0]), "r"(a[1]), "r"(a[2]), "r"(a[3]), "r"(b[0]), "r"(b[1]));
}

// =====================================================================
// transpose: out[C,R] = in[R,C]^T   (R,C multiples of 32)
// =====================================================================
__global__ __launch_bounds__(256) void transpose_kernel(
    const float* __restrict__ in, float* __restrict__ out, int R, int C)
{
    __shared__ float t[32][33];
    int c0 = blockIdx.x * 32, r0 = blockIdx.y * 32;
    int x = threadIdx.x, y = threadIdx.y;
    #pragma unroll
    for (int i = 0; i < 32; i += 8)
        t[y + i][x] = in[(size_t)(r0 + y + i) * C + c0 + x];
    __syncthreads();
    #pragma unroll
    for (int i = 0; i < 32; i += 8)
        out[(size_t)(c0 + y + i) * R + r0 + x] = t[x][y + i];
}

// batched 3-matrix transpose (Wq, Wk, Wv -> slices of g_wqkvt), each DD x DD
__global__ __launch_bounds__(256) void transpose3_kernel(
    const float* __restrict__ s0, const float* __restrict__ s1,
    const float* __restrict__ s2, float* __restrict__ out)
{
    __shared__ float t[32][33];
    const float* in = (blockIdx.z == 0) ? s0 : (blockIdx.z == 1) ? s1 : s2;
    float* o = out + (size_t)blockIdx.z * DD * DD;
    int c0 = blockIdx.x * 32, r0 = blockIdx.y * 32;
    int x = threadIdx.x, y = threadIdx.y;
    #pragma unroll
    for (int i = 0; i < 32; i += 8)
        t[y + i][x] = in[(size_t)(r0 + y + i) * DD + c0 + x];
    __syncthreads();
    #pragma unroll
    for (int i = 0; i < 32; i += 8)
        o[(size_t)(c0 + y + i) * DD + r0 + x] = t[x][y + i];
}

// =====================================================================
// LayerNorm: one block (256 thr) per row, D=768 = 3 elems/thread
// =====================================================================
__global__ __launch_bounds__(256) void layernorm_kernel(
    const float* __restrict__ x, const float* __restrict__ gamma,
    const float* __restrict__ beta, float* __restrict__ out)
{
    int row = blockIdx.x;
    int tid = threadIdx.x;
    const float* xr = x + (size_t)row * DD;

    float v0 = xr[tid], v1 = xr[tid + 256], v2 = xr[tid + 512];
    float s = v0 + v1 + v2;

    __shared__ float red[8];
    __shared__ float mu_s, rs_s;

    #pragma unroll
    for (int off = 16; off; off >>= 1) s += __shfl_xor_sync(0xffffffffu, s, off);
    if ((tid & 31) == 0) red[tid >> 5] = s;
    __syncthreads();
    if (tid == 0) {
        float t = 0.f;
        #pragma unroll
        for (int i = 0; i < 8; i++) t += red[i];
        mu_s = t * (1.0f / (float)DD);
    }
    __syncthreads();
    float mu = mu_s;
    float d0 = v0 - mu, d1 = v1 - mu, d2 = v2 - mu;
    float q = d0 * d0 + d1 * d1 + d2 * d2;
    #pragma unroll
    for (int off = 16; off; off >>= 1) q += __shfl_xor_sync(0xffffffffu, q, off);
    if ((tid & 31) == 0) red[tid >> 5] = q;
    __syncthreads();
    if (tid == 0) {
        float t = 0.f;
        #pragma unroll
        for (int i = 0; i < 8; i++) t += red[i];
        rs_s = rsqrtf(t * (1.0f / (float)DD) + EPSV);
    }
    __syncthreads();
    float rs = rs_s;
    float* orow = out + (size_t)row * DD;
    orow[tid]       = d0 * rs * gamma[tid]       + beta[tid];
    orow[tid + 256] = d1 * rs * gamma[tid + 256] + beta[tid + 256];
    orow[tid + 512] = d2 * rs * gamma[tid + 512] + beta[tid + 512];
}

// =====================================================================
// mma.sync tf32 GEMM: C[M,N] = alpha*A[M,K]@B + bias + relu + res
//   A: [M,K] row-major fp32 ; Bt: [N,K] row-major fp32 (pre-transposed)
//   block 128x128, K chunks of 32, DOUBLE-BUFFERED smem (1 sync/chunk),
//   8 warps (2x4) of 64x32 warp tiles, m16n8k8 tf32 mma,
//   fragment-native smem with rotation swizzle (conflict-free STS/LDS).
//   QKVS: per-column-segment alpha (cols<768 scaled, rest unit) for fused QKV.
// =====================================================================
template<bool BIAS, bool RELU, bool RES, bool QKVS>
__global__ __launch_bounds__(256) void mma_gemm(
    int M, int N, int K, float alpha,
    const float* __restrict__ A, const float* __restrict__ Bt,
    const float* __restrict__ bias, const float* __restrict__ res,
    float* __restrict__ C)
{
    __shared__ uint32_t As[2][4096];   // 16KB x2
    __shared__ uint32_t Bs[2][4096];   // 16KB x2

    const int tid  = threadIdx.x;
    const int lane = tid & 31, wid = tid >> 5;
    const int g = lane >> 2, t4 = lane & 3;
    const int wm = wid & 1, wn = wid >> 1;       // warp grid 2 (m) x 4 (n)
    const int brow = blockIdx.y * 128;
    const int bcol = blockIdx.x * 128;

    // ---- per-i gmem/smem store geometry (i = 0..3, f = tid + 256*i) ----
    int rowi[4], smA[4], smB[4], kofs[4];
    #pragma unroll
    for (int i = 0; i < 4; i++) {
        int f = tid + i * 256;
        int r = f >> 3, j = f & 7;           // r: tile row 0..127, j: k-group 0..7
        int ks = j >> 1, chi = j & 1;
        rowi[i] = r;
        kofs[i] = j * 4;
        int mt = r >> 4, hi = (r >> 3) & 1, gg = r & 7;
        int slot = (gg * 4 + 8 * ks + 4 * chi) & 31;     // rotation swizzle
        smA[i] = ((mt * 4 + ks) * 4 + (hi + 2 * chi)) * 32 + slot;
        int nt = r >> 3;
        smB[i] = ((nt * 4 + ks) * 2 + chi) * 32 + (((r & 7) * 4 + 8 * ks + 4 * chi) & 31);
    }

    float acc[4][4][4];
    #pragma unroll
    for (int mt = 0; mt < 4; mt++)
        #pragma unroll
        for (int nt = 0; nt < 4; nt++)
            #pragma unroll
            for (int r = 0; r < 4; r++) acc[mt][nt][r] = 0.f;

    const int nc = K >> 5;
    float4 va[4], vb[4];

    // prologue: load + stage chunk 0
    #pragma unroll
    for (int i = 0; i < 4; i++) {
        va[i] = *(const float4*)&A [(size_t)(brow + rowi[i]) * K + kofs[i]];
        vb[i] = *(const float4*)&Bt[(size_t)(bcol + rowi[i]) * K + kofs[i]];
    }
    #pragma unroll
    for (int i = 0; i < 4; i++) {
        uint4 ua; ua.x = f2tf32(va[i].x); ua.y = f2tf32(va[i].y); ua.z = f2tf32(va[i].z); ua.w = f2tf32(va[i].w);
        *(uint4*)&As[0][smA[i]] = ua;
        uint4 ub; ub.x = f2tf32(vb[i].x); ub.y = f2tf32(vb[i].y); ub.z = f2tf32(vb[i].z); ub.w = f2tf32(vb[i].w);
        *(uint4*)&Bs[0][smB[i]] = ub;
    }
    __syncthreads();

    for (int ch = 0; ch < nc; ch++) {
        const bool more = (ch + 1 < nc);
        const int s = ch & 1;
        if (more) {
            const int k0 = (ch + 1) << 5;
            #pragma unroll
            for (int i = 0; i < 4; i++) {
                va[i] = *(const float4*)&A [(size_t)(brow + rowi[i]) * K + k0 + kofs[i]];
                vb[i] = *(const float4*)&Bt[(size_t)(bcol + rowi[i]) * K + k0 + kofs[i]];
            }
        }

        // ---- MMA over the 32-K chunk from stage s ----
        const uint32_t* Ap = As[s];
        const uint32_t* Bp = Bs[s];
        #pragma unroll
        for (int ks = 0; ks < 4; ks++) {
            uint32_t af[4][4], bf[4][2];
            #pragma unroll
            for (int mt = 0; mt < 4; mt++) {
                const int mtg = wm * 4 + mt;
                #pragma unroll
                for (int r = 0; r < 4; r++) {
                    int slot = (lane + 8 * ks + 4 * (r >> 1)) & 31;
                    af[mt][r] = Ap[((mtg * 4 + ks) * 4 + r) * 32 + slot];
                }
            }
            #pragma unroll
            for (int nt = 0; nt < 4; nt++) {
                const int ntg = wn * 4 + nt;
                #pragma unroll
                for (int r = 0; r < 2; r++) {
                    int slot = (lane + 8 * ks + 4 * r) & 31;
                    bf[nt][r] = Bp[((ntg * 4 + ks) * 2 + r) * 32 + slot];
                }
            }
            #pragma unroll
            for (int mt = 0; mt < 4; mt++)
                #pragma unroll
                for (int nt = 0; nt < 4; nt++)
                    mma8(acc[mt][nt], af[mt], bf[nt]);
        }

        if (more) {
            // stage chunk ch+1 into the other buffer (its last readers finished
            // at the sync that ended iteration ch-1)
            #pragma unroll
            for (int i = 0; i < 4; i++) {
                uint4 ua; ua.x = f2tf32(va[i].x); ua.y = f2tf32(va[i].y); ua.z = f2tf32(va[i].z); ua.w = f2tf32(va[i].w);
                *(uint4*)&As[s ^ 1][smA[i]] = ua;
                uint4 ub; ub.x = f2tf32(vb[i].x); ub.y = f2tf32(vb[i].y); ub.z = f2tf32(vb[i].z); ub.w = f2tf32(vb[i].w);
                *(uint4*)&Bs[s ^ 1][smB[i]] = ub;
            }
            __syncthreads();
        }
    }

    // ---- epilogue ----
    const float aeff = QKVS ? ((bcol < DD) ? alpha : 1.0f) : alpha;
    #pragma unroll
    for (int mt = 0; mt < 4; mt++) {
        const int row0 = brow + wm * 64 + mt * 16 + g;
        const int row1 = row0 + 8;
        #pragma unroll
        for (int nt = 0; nt < 4; nt++) {
            const int col = bcol + wn * 32 + nt * 8 + t4 * 2;
            float2 lo, hi;
            lo.x = acc[mt][nt][0] * aeff; lo.y = acc[mt][nt][1] * aeff;
            hi.x = acc[mt][nt][2] * aeff; hi.y = acc[mt][nt][3] * aeff;
            if (BIAS) {
                const float2 bb = *(const float2*)&bias[col];
                lo.x += bb.x; lo.y += bb.y; hi.x += bb.x; hi.y += bb.y;
            }
            if (RELU) {
                lo.x = fmaxf(lo.x, 0.f); lo.y = fmaxf(lo.y, 0.f);
                hi.x = fmaxf(hi.x, 0.f); hi.y = fmaxf(hi.y, 0.f);
            }
            if (RES) {
                const float2 r0 = *(const float2*)&res[(size_t)row0 * N + col];
                const float2 r1 = *(const float2*)&res[(size_t)row1 * N + col];
                lo.x += r0.x; lo.y += r0.y; hi.x += r1.x; hi.y += r1.y;
            }
            *(float2*)&C[(size_t)row0 * N + col] = lo;
            *(float2*)&C[(size_t)row1 * N + col] = hi;
        }
    }
}

// =====================================================================
// BigBird flash attention
//   grid (NB=64, H=12, B=2), 256 threads (8 warps), warp w owns rows w+8i.
//   q/k/v live in the fused QKV buffer: row stride QKVD.
// =====================================================================
struct PlanT { int v[(NBB - 2) * 8]; };

__global__ __launch_bounds__(256) void attn_kernel(
    const float* __restrict__ q, const float* __restrict__ k,
    const float* __restrict__ v, const PlanT plan,
    float* __restrict__ ctx)
{
    __shared__ float Qs[64 * 64];   // 16 KB
    __shared__ float Ks[32 * 68];   // padded: conflict-free lane-major reads
    __shared__ float Vs[32 * 64];
    __shared__ float Ps[64 * 33];   // padded P stage

    const int qb = blockIdx.x, h = blockIdx.y, b = blockIdx.z;
    const int tid = threadIdx.x;
    const int w = tid >> 5, lane = tid & 31;

    // load Q tile (pre-scaled by 1/sqrt(HD) in the fused QKV GEMM)
    const size_t qbase = ((size_t)(b * LL + qb * 64)) * QKVD + h * HDD;
    #pragma unroll
    for (int i = 0; i < 4; i++) {
        int f = tid + i * 256;        // 1024 float4s total
        int r = f >> 4, d4 = (f & 15) * 4;
        *(float4*)&Qs[r * 64 + d4] = *(const float4*)&q[qbase + (size_t)r * QKVD + d4];
    }

    float mreg[8], lreg[8], o0[8], o1[8];
    #pragma unroll
    for (int i = 0; i < 8; i++) { mreg[i] = -1e30f; lreg[i] = 0.f; o0[i] = 0.f; o1[i] = 0.f; }

    const int nkb = (qb == 0 || qb == NBB - 1) ? NBB : 8;

    for (int kbi = 0; kbi < nkb; kbi++) {
        int kb = (nkb == NBB) ? kbi : plan.v[(qb - 1) * 8 + kbi];
        for (int half = 0; half < 2; half++) {
            __syncthreads();   // protect Ks/Vs (and first-iter Qs) from prior consumers
            const size_t kbase = ((size_t)(b * LL + kb * 64 + half * 32)) * QKVD + h * HDD;
            #pragma unroll
            for (int i = 0; i < 2; i++) {
                int f = tid + i * 256;    // 512 float4s
                int c = f >> 4, d4 = (f & 15) * 4;
                *(float4*)&Ks[c * 68 + d4] = *(const float4*)&k[kbase + (size_t)c * QKVD + d4];
                *(float4*)&Vs[c * 64 + d4] = *(const float4*)&v[kbase + (size_t)c * QKVD + d4];
            }
            __syncthreads();

            // ---- QK^T + online softmax, one row at a time per warp ----
            #pragma unroll
            for (int i = 0; i < 8; i++) {
                int r = w + i * 8;
                const float4* qr = (const float4*)&Qs[r * 64];
                const float4* kr = (const float4*)&Ks[lane * 68];
                float s = 0.f;
                #pragma unroll
                for (int d4 = 0; d4 < 16; d4++) {
                    float4 a = qr[d4]; float4 bb = kr[d4];
                    s += a.x * bb.x + a.y * bb.y + a.z * bb.z + a.w * bb.w;
                }
                float cm = s;
                #pragma unroll
                for (int off = 16; off; off >>= 1)
                    cm = fmaxf(cm, __shfl_xor_sync(0xffffffffu, cm, off));
                float mn = fmaxf(mreg[i], cm);
                float sc = __expf(mreg[i] - mn);
                float p  = __expf(s - mn);
                float ps = p;
                #pragma unroll
                for (int off = 16; off; off >>= 1)
                    ps += __shfl_xor_sync(0xffffffffu, ps, off);
                lreg[i] = lreg[i] * sc + ps;
                mreg[i] = mn;
                o0[i] *= sc; o1[i] *= sc;
                Ps[r * 33 + lane] = p;
            }
            __syncwarp();

            // ---- P @ V: lane owns output dims (lane, lane+32), 2 rows at a time ----
            #pragma unroll
            for (int i = 0; i < 8; i += 2) {
                int r0 = w + i * 8, r1 = r0 + 8;
                float a0 = o0[i], a1 = o1[i], b0 = o0[i + 1], b1 = o1[i + 1];
                #pragma unroll
                for (int c = 0; c < 32; c++) {
                    float vv0 = Vs[c * 64 + lane];
                    float vv1 = Vs[c * 64 + lane + 32];
                    float p0 = Ps[r0 * 33 + c];
                    float p1 = Ps[r1 * 33 + c];
                    a0 += p0 * vv0; a1 += p0 * vv1;
                    b0 += p1 * vv0; b1 += p1 * vv1;
                }
                o0[i] = a0; o1[i] = a1; o0[i + 1] = b0; o1[i + 1] = b1;
            }
        }
    }

    // write context in [B*L, D] layout (col = h*64 + d) for the Wo GEMM
    const size_t obase = ((size_t)(b * LL + qb * 64)) * DD + h * HDD;
    #pragma unroll
    for (int i = 0; i < 8; i++) {
        int r = w + i * 8;
        float inv = 1.0f / lreg[i];
        ctx[obase + (size_t)r * DD + lane]      = o0[i] * inv;
        ctx[obase + (size_t)r * DD + lane + 32] = o1[i] * inv;
    }
}

// =====================================================================
// host-side numpy MT19937 (legacy RandomState(0)) -> BigBird plan
// =====================================================================
namespace hostmt {
struct MT {
    unsigned int key[624];
    int pos;
};
static void mt_seed(MT& s, unsigned int seed) {
    for (int p = 0; p < 624; p++) {
        s.key[p] = seed;
        seed = 1812433253u * (seed ^ (seed >> 30)) + (unsigned)p + 1u;
    }
    s.pos = 624;
}
static unsigned int mt_next(MT& s) {
    if (s.pos == 624) {
        for (int i = 0; i < 624; i++) {
            unsigned int y = (s.key[i] & 0x80000000u) | (s.key[(i + 1) % 624] & 0x7fffffffu);
            s.key[i] = s.key[(i + 397) % 624] ^ (y >> 1) ^ ((y & 1u) ? 0x9908b0dfu : 0u);
        }
        s.pos = 0;
    }
    unsigned int y = s.key[s.pos++];
    y ^= y >> 11;
    y ^= (y << 7)  & 0x9d2c5680u;
    y ^= (y << 15) & 0xefc60000u;
    y ^= y >> 18;
    return y;
}
static unsigned int mt_interval(MT& s, unsigned int mx) {
    if (mx == 0u) return 0u;
    unsigned int mask = mx;
    mask |= mask >> 1; mask |= mask >> 2; mask |= mask >> 4;
    mask |= mask >> 8; mask |= mask >> 16;
    unsigned int v;
    while ((v = (mt_next(s) & mask)) > mx) { }
    return v;
}
static void make_plan(int* plan) {
    MT st;
    mt_seed(st, 0u);
    for (int i = 1; i <= NBB - 2; i++) {
        int cand[64]; int n = 0;
        for (int j = 0; j < NBB; j++) {
            if (j == 0 || j == NBB - 1 || j == i - 1 || j == i || j == i + 1) continue;
            cand[n++] = j;
        }
        int perm[64];
        for (int j = 0; j < n; j++) perm[j] = j;
        for (int ii = n - 1; ii >= 1; ii--) {
            int j = (int)mt_interval(st, (unsigned)ii);
            int t = perm[ii]; perm[ii] = perm[j]; perm[j] = t;
        }
        int* row = plan + (i - 1) * 8;
        row[0] = 0; row[1] = NBB - 1; row[2] = i - 1; row[3] = i; row[4] = i + 1;
        for (int t = 0; t < 3; t++) row[5 + t] = cand[perm[t]];
    }
}
} // namespace hostmt

// =====================================================================
// launch
// =====================================================================
extern "C" void kernel_launch(void* const* d_in, const int* in_sizes, int n_in,
                              void* d_out, int out_size)
{
    (void)in_sizes; (void)n_in; (void)out_size;
    const float* x    = (const float*)d_in[0];
    const float* ln1s = (const float*)d_in[1];
    const float* ln1b = (const float*)d_in[2];
    const float* Wq   = (const float*)d_in[3];   // [D, H*HD] flat
    const float* Wk   = (const float*)d_in[4];
    const float* Wv   = (const float*)d_in[5];
    const float* Wo   = (const float*)d_in[6];   // [H*HD, D] flat
    const float* ln2s = (const float*)d_in[7];
    const float* ln2b = (const float*)d_in[8];
    const float* W1   = (const float*)d_in[9];   // [D, MLP]
    const float* b1   = (const float*)d_in[10];
    const float* W2   = (const float*)d_in[11];  // [MLP, D]
    const float* b2   = (const float*)d_in[12];
    float* out = (float*)d_out;

    void *ph, *pqkv, *pctx, *px1, *py, *pz;
    void *pwqkvt, *pwot, *pw1t, *pw2t;
    cudaGetSymbolAddress(&ph,    g_h);
    cudaGetSymbolAddress(&pqkv,  g_qkv);
    cudaGetSymbolAddress(&pctx,  g_ctx);
    cudaGetSymbolAddress(&px1,   g_x1);
    cudaGetSymbolAddress(&py,    g_y);
    cudaGetSymbolAddress(&pz,    g_z);
    cudaGetSymbolAddress(&pwqkvt, g_wqkvt);
    cudaGetSymbolAddress(&pwot,  g_wot);
    cudaGetSymbolAddress(&pw1t,  g_w1t);
    cudaGetSymbolAddress(&pw2t,  g_w2t);

    float* fh    = (float*)ph;
    float* fqkv  = (float*)pqkv;
    float* fctx  = (float*)pctx;
    float* fx1   = (float*)px1;
    float* fy    = (float*)py;
    float* fz    = (float*)pz;
    float* wqkvt = (float*)pwqkvt;
    float* wot   = (float*)pwot;
    float* w1t   = (float*)pw1t;
    float* w2t   = (float*)pw2t;

    // host-computed BigBird plan (numpy MT19937 replica) as kernel param
    PlanT plan;
    hostmt::make_plan(plan.v);

    dim3 tb(32, 8);

    // launches 1-5 (so the fused QKV GEMM is launch #6 == ncu -s 5 -c 1 target)
    transpose3_kernel<<<dim3(DD / 32, DD / 32, 3), tb>>>(Wq, Wk, Wv, wqkvt);
    transpose_kernel<<<dim3(DD / 32, DD / 32), tb>>>(Wo, wot, DD, DD);
    transpose_kernel<<<dim3(MLPD / 32, DD / 32), tb>>>(W1, w1t, DD, MLPD);
    transpose_kernel<<<dim3(DD / 32, MLPD / 32), tb>>>(W2, w2t, MLPD, DD);
    layernorm_kernel<<<ROWS, 256>>>(x, ln1s, ln1b, fh);

    // 6th launch: fused QKV GEMM, N=2304, q-segment scaled by 0.125
    dim3 gqkv(QKVD / 128, ROWS / 128);
    mma_gemm<false, false, false, true><<<gqkv, 256>>>(ROWS, QKVD, DD, 0.125f, fh, wqkvt, nullptr, nullptr, fqkv);

    // BigBird attention -> ctx [B*L, D]
    attn_kernel<<<dim3(NBB, HH, BB), 256>>>(fqkv, fqkv + DD, fqkv + 2 * DD, plan, fctx);

    // x1 = ctx @ Wo + x
    dim3 gdd(DD / 128, ROWS / 128);
    mma_gemm<false, false, true, false><<<gdd, 256>>>(ROWS, DD, DD, 1.0f, fctx, wot, nullptr, x, fx1);

    // y = LN2(x1)
    layernorm_kernel<<<ROWS, 256>>>(fx1, ln2s, ln2b, fy);

    // z = relu(y @ W1 + b1)
    dim3 gm1(MLPD / 128, ROWS / 128);
    mma_gemm<true, true, false, false><<<gm1, 256>>>(ROWS, MLPD, DD, 1.0f, fy, w1t, b1, nullptr, fz);

    // out = z @ W2 + b2 + x1
    mma_gemm<true, false, true, false><<<gdd, 256>>>(ROWS, DD, MLPD, 1.0f, fz, w2t, b2, fx1, out);
}

// round 5
// speedup vs baseline: 2.5563x; 1.0990x over previous
#include <cuda_runtime.h>
#include <cuda_fp16.h>
#include <cstdint>

// ---------------- problem dims ----------------
#define BB   2
#define LL   4096
#define DD   768
#define HH   12
#define HDD  64
#define NBB  64
#define MLPD 3072
#define ROWS (BB*LL)      // 8192
#define QKVD (3*DD)       // 2304
#define EPSV 1e-6f

// ---------------- scratch (device globals; no allocation allowed) ------------
__device__ float g_h  [ROWS*DD];
__device__ float g_qkv[ROWS*QKVD];
__device__ float g_ctx[ROWS*DD];
__device__ float g_x1 [ROWS*DD];
__device__ float g_y  [ROWS*DD];
__device__ float g_z  [ROWS*MLPD];
// transposed (K-major) weights, pre-converted to half
__device__ __half g_wqkvt[QKVD*DD];   // rows: [Wq^T ; Wk^T ; Wv^T]
__device__ __half g_wot[DD*DD];
__device__ __half g_w1t[MLPD*DD];
__device__ __half g_w2t[DD*MLPD];

// =====================================================================
// helpers
// =====================================================================
__device__ __forceinline__ void mma16(float* d, const uint32_t* a, const uint32_t* b) {
    asm volatile(
        "mma.sync.aligned.m16n8k16.row.col.f32.f16.f16.f32 "
        "{%0,%1,%2,%3}, {%4,%5,%6,%7}, {%8,%9}, {%0,%1,%2,%3};"
        : "+f"(d[0]), "+f"(d[1]), "+f"(d[2]), "+f"(d[3])
        : "r"(a[0]), "r"(a[1]), "r"(a[2]), "r"(a[3]), "r"(b[0]), "r"(b[1]));
}

__device__ __forceinline__ uint32_t pack_h2(float lo, float hi) {
    __half2 h = __floats2half2_rn(lo, hi);    // .x = lo, .y = hi
    return *reinterpret_cast<uint32_t*>(&h);
}

// =====================================================================
// transpose (fp32 in -> half out): out[C,R] = half(in[R,C]^T)
// =====================================================================
__global__ __launch_bounds__(256) void transpose_h_kernel(
    const float* __restrict__ in, __half* __restrict__ out, int R, int C)
{
    __shared__ float t[32][33];
    int c0 = blockIdx.x * 32, r0 = blockIdx.y * 32;
    int x = threadIdx.x, y = threadIdx.y;
    #pragma unroll
    for (int i = 0; i < 32; i += 8)
        t[y + i][x] = in[(size_t)(r0 + y + i) * C + c0 + x];
    __syncthreads();
    #pragma unroll
    for (int i = 0; i < 32; i += 8)
        out[(size_t)(c0 + y + i) * R + r0 + x] = __float2half(t[x][y + i]);
}

// batched 3-matrix transpose (Wq, Wk, Wv -> slices of g_wqkvt), each DD x DD
__global__ __launch_bounds__(256) void transpose3_h_kernel(
    const float* __restrict__ s0, const float* __restrict__ s1,
    const float* __restrict__ s2, __half* __restrict__ out)
{
    __shared__ float t[32][33];
    const float* in = (blockIdx.z == 0) ? s0 : (blockIdx.z == 1) ? s1 : s2;
    __half* o = out + (size_t)blockIdx.z * DD * DD;
    int c0 = blockIdx.x * 32, r0 = blockIdx.y * 32;
    int x = threadIdx.x, y = threadIdx.y;
    #pragma unroll
    for (int i = 0; i < 32; i += 8)
        t[y + i][x] = in[(size_t)(r0 + y + i) * DD + c0 + x];
    __syncthreads();
    #pragma unroll
    for (int i = 0; i < 32; i += 8)
        o[(size_t)(c0 + y + i) * DD + r0 + x] = __float2half(t[x][y + i]);
}

// =====================================================================
// LayerNorm: one block (256 thr) per row, D=768 = 3 elems/thread
// =====================================================================
__global__ __launch_bounds__(256) void layernorm_kernel(
    const float* __restrict__ x, const float* __restrict__ gamma,
    const float* __restrict__ beta, float* __restrict__ out)
{
    int row = blockIdx.x;
    int tid = threadIdx.x;
    const float* xr = x + (size_t)row * DD;

    float v0 = xr[tid], v1 = xr[tid + 256], v2 = xr[tid + 512];
    float s = v0 + v1 + v2;

    __shared__ float red[8];
    __shared__ float mu_s, rs_s;

    #pragma unroll
    for (int off = 16; off; off >>= 1) s += __shfl_xor_sync(0xffffffffu, s, off);
    if ((tid & 31) == 0) red[tid >> 5] = s;
    __syncthreads();
    if (tid == 0) {
        float t = 0.f;
        #pragma unroll
        for (int i = 0; i < 8; i++) t += red[i];
        mu_s = t * (1.0f / (float)DD);
    }
    __syncthreads();
    float mu = mu_s;
    float d0 = v0 - mu, d1 = v1 - mu, d2 = v2 - mu;
    float q = d0 * d0 + d1 * d1 + d2 * d2;
    #pragma unroll
    for (int off = 16; off; off >>= 1) q += __shfl_xor_sync(0xffffffffu, q, off);
    if ((tid & 31) == 0) red[tid >> 5] = q;
    __syncthreads();
    if (tid == 0) {
        float t = 0.f;
        #pragma unroll
        for (int i = 0; i < 8; i++) t += red[i];
        rs_s = rsqrtf(t * (1.0f / (float)DD) + EPSV);
    }
    __syncthreads();
    float rs = rs_s;
    float* orow = out + (size_t)row * DD;
    orow[tid]       = d0 * rs * gamma[tid]       + beta[tid];
    orow[tid + 256] = d1 * rs * gamma[tid + 256] + beta[tid + 256];
    orow[tid + 512] = d2 * rs * gamma[tid + 512] + beta[tid + 512];
}

// =====================================================================
// fp16 mma.sync GEMM: C[M,N] = alpha*A[M,K]@B + bias + relu + res
//   A: [M,K] row-major fp32 (converted to half in-kernel)
//   Bt: [N,K] row-major HALF (pre-transposed/converted)
//   block 128x128, K chunks of 32, double-buffered smem (1 sync/chunk),
//   8 warps (2x4) of 64x32 warp tiles, m16n8k16 fp16 mma, fp32 accum,
//   fragment-native smem with per-(ks,reg) rotation (conflict-free STS/LDS).
//   QKVS: per-column-segment alpha (cols<768 scaled) for the fused QKV GEMM.
// =====================================================================
template<bool BIAS, bool RELU, bool RES, bool QKVS>
__global__ __launch_bounds__(256, 2) void mma_gemm(
    int M, int N, int K, float alpha,
    const float* __restrict__ A, const __half* __restrict__ Bt,
    const float* __restrict__ bias, const float* __restrict__ res,
    float* __restrict__ C)
{
    // A frag store: ((mtg*2+ks)*4+reg)*32 + slot   (mtg 0..7, ks 0..1, reg 0..3)
    // B frag store: ((ntg*2+ks)*2+reg)*32 + slot   (ntg 0..15, ks 0..1, reg 0..1)
    __shared__ uint32_t As2[2][2048];   // 8KB x2
    __shared__ uint32_t Bs2[2][2048];   // 8KB x2

    const int tid  = threadIdx.x;
    const int lane = tid & 31, wid = tid >> 5;
    const int g = lane >> 2, t4 = lane & 3;
    const int wm = wid & 1, wn = wid >> 1;       // warp grid 2 (m) x 4 (n)
    const int brow = blockIdx.y * 128;
    const int bcol = blockIdx.x * 128;

    // ---- staging geometry: thread handles one (row, ks16) of A and of B ----
    const int sr   = tid >> 1;        // tile row 0..127
    const int sks  = tid & 1;         // k-step (16 halves)
    const int smtg = sr >> 4, sg = sr & 7, shi = (sr >> 3) & 1;
    const int sntg = sr >> 3;
    int aidx[8], bidx[8];
    #pragma unroll
    for (int c = 0; c < 8; c++) {
        int rega = 2 * (c >= 4) + shi;                      // R(ks,reg)=ks+2*(reg&1)
        aidx[c] = ((smtg * 2 + sks) * 4 + rega) * 32 + ((sg * 4 + (c & 3) + sks + 2 * shi) & 31);
        int regb = (c >= 4);                                 // Rb(ks,ntg)=ks+2*(ntg&1)
        bidx[c] = ((sntg * 2 + sks) * 2 + regb) * 32 + ((sg * 4 + (c & 3) + sks + 2 * (sntg & 1)) & 31);
    }
    const float*  Ag = A  + (size_t)(brow + sr) * K + sks * 16;
    const __half* Bg = Bt + (size_t)(bcol + sr) * K + sks * 16;

    float acc[4][4][4];
    #pragma unroll
    for (int mt = 0; mt < 4; mt++)
        #pragma unroll
        for (int nt = 0; nt < 4; nt++)
            #pragma unroll
            for (int r = 0; r < 4; r++) acc[mt][nt][r] = 0.f;

    const int nc = K >> 5;
    float4 va[4];
    uint4  vb[2];

    // prologue: load + stage chunk 0
    #pragma unroll
    for (int i = 0; i < 4; i++) va[i] = *(const float4*)(Ag + i * 4);
    vb[0] = *(const uint4*)(Bg);
    vb[1] = *(const uint4*)(Bg + 8);
    {
        const float* af = (const float*)va;
        const uint32_t* bw = (const uint32_t*)vb;
        #pragma unroll
        for (int c = 0; c < 8; c++) {
            As2[0][aidx[c]] = pack_h2(af[2 * c], af[2 * c + 1]);
            Bs2[0][bidx[c]] = bw[c];
        }
    }
    __syncthreads();

    for (int ch = 0; ch < nc; ch++) {
        const bool more = (ch + 1 < nc);
        const int s = ch & 1;
        if (more) {
            const int k0 = (ch + 1) << 5;
            #pragma unroll
            for (int i = 0; i < 4; i++) va[i] = *(const float4*)(Ag + k0 + i * 4);
            vb[0] = *(const uint4*)(Bg + k0);
            vb[1] = *(const uint4*)(Bg + k0 + 8);
        }

        // ---- MMA over the 32-K chunk from stage s ----
        const uint32_t* Ap = As2[s];
        const uint32_t* Bp = Bs2[s];
        #pragma unroll
        for (int ks = 0; ks < 2; ks++) {
            uint32_t af[4][4], bf[4][2];
            #pragma unroll
            for (int mt = 0; mt < 4; mt++) {
                const int mtg = wm * 4 + mt;
                #pragma unroll
                for (int r = 0; r < 4; r++)
                    af[mt][r] = Ap[((mtg * 2 + ks) * 4 + r) * 32 + ((lane + ks + 2 * (r & 1)) & 31)];
            }
            #pragma unroll
            for (int nt = 0; nt < 4; nt++) {
                const int ntg = wn * 4 + nt;
                #pragma unroll
                for (int r = 0; r < 2; r++)
                    bf[nt][r] = Bp[((ntg * 2 + ks) * 2 + r) * 32 + ((lane + ks + 2 * (ntg & 1)) & 31)];
            }
            #pragma unroll
            for (int mt = 0; mt < 4; mt++)
                #pragma unroll
                for (int nt = 0; nt < 4; nt++)
                    mma16(acc[mt][nt], af[mt], bf[nt]);
        }

        if (more) {
            const float* af = (const float*)va;
            const uint32_t* bw = (const uint32_t*)vb;
            uint32_t* An = As2[s ^ 1];
            uint32_t* Bn = Bs2[s ^ 1];
            #pragma unroll
            for (int c = 0; c < 8; c++) {
                An[aidx[c]] = pack_h2(af[2 * c], af[2 * c + 1]);
                Bn[bidx[c]] = bw[c];
            }
            __syncthreads();
        }
    }

    // ---- epilogue (fp32) ----
    const float aeff = QKVS ? ((bcol < DD) ? alpha : 1.0f) : alpha;
    #pragma unroll
    for (int mt = 0; mt < 4; mt++) {
        const int row0 = brow + wm * 64 + mt * 16 + g;
        const int row1 = row0 + 8;
        #pragma unroll
        for (int nt = 0; nt < 4; nt++) {
            const int col = bcol + wn * 32 + nt * 8 + t4 * 2;
            float2 lo, hi;
            lo.x = acc[mt][nt][0] * aeff; lo.y = acc[mt][nt][1] * aeff;
            hi.x = acc[mt][nt][2] * aeff; hi.y = acc[mt][nt][3] * aeff;
            if (BIAS) {
                const float2 bb = *(const float2*)&bias[col];
                lo.x += bb.x; lo.y += bb.y; hi.x += bb.x; hi.y += bb.y;
            }
            if (RELU) {
                lo.x = fmaxf(lo.x, 0.f); lo.y = fmaxf(lo.y, 0.f);
                hi.x = fmaxf(hi.x, 0.f); hi.y = fmaxf(hi.y, 0.f);
            }
            if (RES) {
                const float2 r0 = *(const float2*)&res[(size_t)row0 * N + col];
                const float2 r1 = *(const float2*)&res[(size_t)row1 * N + col];
                lo.x += r0.x; lo.y += r0.y; hi.x += r1.x; hi.y += r1.y;
            }
            *(float2*)&C[(size_t)row0 * N + col] = lo;
            *(float2*)&C[(size_t)row1 * N + col] = hi;
        }
    }
}

// =====================================================================
// BigBird flash attention (fp32)
//   grid (NB=64, H=12, B=2), 256 threads (8 warps), warp w owns rows w+8i.
//   q/k/v live in the fused QKV buffer: row stride QKVD.
// =====================================================================
struct PlanT { int v[(NBB - 2) * 8]; };

__global__ __launch_bounds__(256) void attn_kernel(
    const float* __restrict__ q, const float* __restrict__ k,
    const float* __restrict__ v, const PlanT plan,
    float* __restrict__ ctx)
{
    __shared__ float Qs[64 * 64];   // 16 KB
    __shared__ float Ks[32 * 68];   // padded: conflict-free lane-major reads
    __shared__ float Vs[32 * 64];
    __shared__ float Ps[64 * 33];   // padded P stage

    const int qb = blockIdx.x, h = blockIdx.y, b = blockIdx.z;
    const int tid = threadIdx.x;
    const int w = tid >> 5, lane = tid & 31;

    // load Q tile (pre-scaled by 1/sqrt(HD) in the fused QKV GEMM)
    const size_t qbase = ((size_t)(b * LL + qb * 64)) * QKVD + h * HDD;
    #pragma unroll
    for (int i = 0; i < 4; i++) {
        int f = tid + i * 256;        // 1024 float4s total
        int r = f >> 4, d4 = (f & 15) * 4;
        *(float4*)&Qs[r * 64 + d4] = *(const float4*)&q[qbase + (size_t)r * QKVD + d4];
    }

    float mreg[8], lreg[8], o0[8], o1[8];
    #pragma unroll
    for (int i = 0; i < 8; i++) { mreg[i] = -1e30f; lreg[i] = 0.f; o0[i] = 0.f; o1[i] = 0.f; }

    const int nkb = (qb == 0 || qb == NBB - 1) ? NBB : 8;

    for (int kbi = 0; kbi < nkb; kbi++) {
        int kb = (nkb == NBB) ? kbi : plan.v[(qb - 1) * 8 + kbi];
        for (int half = 0; half < 2; half++) {
            __syncthreads();   // protect Ks/Vs (and first-iter Qs) from prior consumers
            const size_t kbase = ((size_t)(b * LL + kb * 64 + half * 32)) * QKVD + h * HDD;
            #pragma unroll
            for (int i = 0; i < 2; i++) {
                int f = tid + i * 256;    // 512 float4s
                int c = f >> 4, d4 = (f & 15) * 4;
                *(float4*)&Ks[c * 68 + d4] = *(const float4*)&k[kbase + (size_t)c * QKVD + d4];
                *(float4*)&Vs[c * 64 + d4] = *(const float4*)&v[kbase + (size_t)c * QKVD + d4];
            }
            __syncthreads();

            // ---- QK^T + online softmax, one row at a time per warp ----
            #pragma unroll
            for (int i = 0; i < 8; i++) {
                int r = w + i * 8;
                const float4* qr = (const float4*)&Qs[r * 64];
                const float4* kr = (const float4*)&Ks[lane * 68];
                float s = 0.f;
                #pragma unroll
                for (int d4 = 0; d4 < 16; d4++) {
                    float4 a = qr[d4]; float4 bb = kr[d4];
                    s += a.x * bb.x + a.y * bb.y + a.z * bb.z + a.w * bb.w;
                }
                float cm = s;
                #pragma unroll
                for (int off = 16; off; off >>= 1)
                    cm = fmaxf(cm, __shfl_xor_sync(0xffffffffu, cm, off));
                float mn = fmaxf(mreg[i], cm);
                float sc = __expf(mreg[i] - mn);
                float p  = __expf(s - mn);
                float ps = p;
                #pragma unroll
                for (int off = 16; off; off >>= 1)
                    ps += __shfl_xor_sync(0xffffffffu, ps, off);
                lreg[i] = lreg[i] * sc + ps;
                mreg[i] = mn;
                o0[i] *= sc; o1[i] *= sc;
                Ps[r * 33 + lane] = p;
            }
            __syncwarp();

            // ---- P @ V: lane owns output dims (lane, lane+32), 2 rows at a time ----
            #pragma unroll
            for (int i = 0; i < 8; i += 2) {
                int r0 = w + i * 8, r1 = r0 + 8;
                float a0 = o0[i], a1 = o1[i], b0 = o0[i + 1], b1 = o1[i + 1];
                #pragma unroll
                for (int c = 0; c < 32; c++) {
                    float vv0 = Vs[c * 64 + lane];
                    float vv1 = Vs[c * 64 + lane + 32];
                    float p0 = Ps[r0 * 33 + c];
                    float p1 = Ps[r1 * 33 + c];
                    a0 += p0 * vv0; a1 += p0 * vv1;
                    b0 += p1 * vv0; b1 += p1 * vv1;
                }
                o0[i] = a0; o1[i] = a1; o0[i + 1] = b0; o1[i + 1] = b1;
            }
        }
    }

    // write context in [B*L, D] layout (col = h*64 + d) for the Wo GEMM
    const size_t obase = ((size_t)(b * LL + qb * 64)) * DD + h * HDD;
    #pragma unroll
    for (int i = 0; i < 8; i++) {
        int r = w + i * 8;
        float inv = 1.0f / lreg[i];
        ctx[obase + (size_t)r * DD + lane]      = o0[i] * inv;
        ctx[obase + (size_t)r * DD + lane + 32] = o1[i] * inv;
    }
}

// =====================================================================
// host-side numpy MT19937 (legacy RandomState(0)) -> BigBird plan
// =====================================================================
namespace hostmt {
struct MT {
    unsigned int key[624];
    int pos;
};
static void mt_seed(MT& s, unsigned int seed) {
    for (int p = 0; p < 624; p++) {
        s.key[p] = seed;
        seed = 1812433253u * (seed ^ (seed >> 30)) + (unsigned)p + 1u;
    }
    s.pos = 624;
}
static unsigned int mt_next(MT& s) {
    if (s.pos == 624) {
        for (int i = 0; i < 624; i++) {
            unsigned int y = (s.key[i] & 0x80000000u) | (s.key[(i + 1) % 624] & 0x7fffffffu);
            s.key[i] = s.key[(i + 397) % 624] ^ (y >> 1) ^ ((y & 1u) ? 0x9908b0dfu : 0u);
        }
        s.pos = 0;
    }
    unsigned int y = s.key[s.pos++];
    y ^= y >> 11;
    y ^= (y << 7)  & 0x9d2c5680u;
    y ^= (y << 15) & 0xefc60000u;
    y ^= y >> 18;
    return y;
}
static unsigned int mt_interval(MT& s, unsigned int mx) {
    if (mx == 0u) return 0u;
    unsigned int mask = mx;
    mask |= mask >> 1; mask |= mask >> 2; mask |= mask >> 4;
    mask |= mask >> 8; mask |= mask >> 16;
    unsigned int v;
    while ((v = (mt_next(s) & mask)) > mx) { }
    return v;
}
static void make_plan(int* plan) {
    MT st;
    mt_seed(st, 0u);
    for (int i = 1; i <= NBB - 2; i++) {
        int cand[64]; int n = 0;
        for (int j = 0; j < NBB; j++) {
            if (j == 0 || j == NBB - 1 || j == i - 1 || j == i || j == i + 1) continue;
            cand[n++] = j;
        }
        int perm[64];
        for (int j = 0; j < n; j++) perm[j] = j;
        for (int ii = n - 1; ii >= 1; ii--) {
            int j = (int)mt_interval(st, (unsigned)ii);
            int t = perm[ii]; perm[ii] = perm[j]; perm[j] = t;
        }
        int* row = plan + (i - 1) * 8;
        row[0] = 0; row[1] = NBB - 1; row[2] = i - 1; row[3] = i; row[4] = i + 1;
        for (int t = 0; t < 3; t++) row[5 + t] = cand[perm[t]];
    }
}
} // namespace hostmt

// =====================================================================
// launch
// =====================================================================
extern "C" void kernel_launch(void* const* d_in, const int* in_sizes, int n_in,
                              void* d_out, int out_size)
{
    (void)in_sizes; (void)n_in; (void)out_size;
    const float* x    = (const float*)d_in[0];
    const float* ln1s = (const float*)d_in[1];
    const float* ln1b = (const float*)d_in[2];
    const float* Wq   = (const float*)d_in[3];   // [D, H*HD] flat
    const float* Wk   = (const float*)d_in[4];
    const float* Wv   = (const float*)d_in[5];
    const float* Wo   = (const float*)d_in[6];   // [H*HD, D] flat
    const float* ln2s = (const float*)d_in[7];
    const float* ln2b = (const float*)d_in[8];
    const float* W1   = (const float*)d_in[9];   // [D, MLP]
    const float* b1   = (const float*)d_in[10];
    const float* W2   = (const float*)d_in[11];  // [MLP, D]
    const float* b2   = (const float*)d_in[12];
    float* out = (float*)d_out;

    void *ph, *pqkv, *pctx, *px1, *py, *pz;
    void *pwqkvt, *pwot, *pw1t, *pw2t;
    cudaGetSymbolAddress(&ph,    g_h);
    cudaGetSymbolAddress(&pqkv,  g_qkv);
    cudaGetSymbolAddress(&pctx,  g_ctx);
    cudaGetSymbolAddress(&px1,   g_x1);
    cudaGetSymbolAddress(&py,    g_y);
    cudaGetSymbolAddress(&pz,    g_z);
    cudaGetSymbolAddress(&pwqkvt, g_wqkvt);
    cudaGetSymbolAddress(&pwot,  g_wot);
    cudaGetSymbolAddress(&pw1t,  g_w1t);
    cudaGetSymbolAddress(&pw2t,  g_w2t);

    float*  fh    = (float*)ph;
    float*  fqkv  = (float*)pqkv;
    float*  fctx  = (float*)pctx;
    float*  fx1   = (float*)px1;
    float*  fy    = (float*)py;
    float*  fz    = (float*)pz;
    __half* wqkvt = (__half*)pwqkvt;
    __half* wot   = (__half*)pwot;
    __half* w1t   = (__half*)pw1t;
    __half* w2t   = (__half*)pw2t;

    // host-computed BigBird plan (numpy MT19937 replica) as kernel param
    PlanT plan;
    hostmt::make_plan(plan.v);

    dim3 tb(32, 8);

    // #1-#3 (ncu captures my 4th launch -> make it the QKV GEMM)
    transpose3_h_kernel<<<dim3(DD / 32, DD / 32, 3), tb>>>(Wq, Wk, Wv, wqkvt);
    transpose_h_kernel<<<dim3(DD / 32, DD / 32), tb>>>(Wo, wot, DD, DD);
    layernorm_kernel<<<ROWS, 256>>>(x, ln1s, ln1b, fh);

    // #4: fused QKV GEMM, N=2304, q-segment scaled by 0.125
    dim3 gqkv(QKVD / 128, ROWS / 128);
    mma_gemm<false, false, false, true><<<gqkv, 256>>>(ROWS, QKVD, DD, 0.125f, fh, wqkvt, nullptr, nullptr, fqkv);

    // remaining transposes (needed before the MLP GEMMs)
    transpose_h_kernel<<<dim3(MLPD / 32, DD / 32), tb>>>(W1, w1t, DD, MLPD);
    transpose_h_kernel<<<dim3(DD / 32, MLPD / 32), tb>>>(W2, w2t, MLPD, DD);

    // BigBird attention -> ctx [B*L, D]
    attn_kernel<<<dim3(NBB, HH, BB), 256>>>(fqkv, fqkv + DD, fqkv + 2 * DD, plan, fctx);

    // x1 = ctx @ Wo + x
    dim3 gdd(DD / 128, ROWS / 128);
    mma_gemm<false, false, true, false><<<gdd, 256>>>(ROWS, DD, DD, 1.0f, fctx, wot, nullptr, x, fx1);

    // y = LN2(x1)
    layernorm_kernel<<<ROWS, 256>>>(fx1, ln2s, ln2b, fy);

    // z = relu(y @ W1 + b1)
    dim3 gm1(MLPD / 128, ROWS / 128);
    mma_gemm<true, true, false, false><<<gm1, 256>>>(ROWS, MLPD, DD, 1.0f, fy, w1t, b1, nullptr, fz);

    // out = z @ W2 + b2 + x1
    mma_gemm<true, false, true, false><<<gdd, 256>>>(ROWS, DD, MLPD, 1.0f, fz, w2t, b2, fx1, out);
}

// round 7
// speedup vs baseline: 2.7315x; 1.0685x over previous
#include <cuda_runtime.h>
#include <cuda_fp16.h>
#include <cstdint>

// ---------------- problem dims ----------------
#define BB   2
#define LL   4096
#define DD   768
#define HH   12
#define HDD  64
#define NBB  64
#define MLPD 3072
#define ROWS (BB*LL)      // 8192
#define QKVD (3*DD)       // 2304
#define EPSV 1e-6f

// ---------------- scratch (device globals; no allocation allowed) ------------
__device__ float g_h  [ROWS*DD];
__device__ float g_qkv[ROWS*QKVD];
__device__ float g_ctx[ROWS*DD];
__device__ float g_x1 [ROWS*DD];
__device__ float g_y  [ROWS*DD];
__device__ float g_z  [ROWS*MLPD];
// transposed (K-major) weights, pre-converted to half
__device__ __half g_wqkvt[QKVD*DD];   // rows: [Wq^T ; Wk^T ; Wv^T]
__device__ __half g_wot[DD*DD];
__device__ __half g_w1t[MLPD*DD];
__device__ __half g_w2t[DD*MLPD];

// =====================================================================
// helpers
// =====================================================================
__device__ __forceinline__ uint32_t smem_u32(const void* p) {
    uint32_t a;
    asm("{ .reg .u64 t; cvta.to.shared.u64 t, %1; cvt.u32.u64 %0, t; }" : "=r"(a) : "l"(p));
    return a;
}

__device__ __forceinline__ void mma16(float* d, const uint32_t* a, const uint32_t* b) {
    asm volatile(
        "mma.sync.aligned.m16n8k16.row.col.f32.f16.f16.f32 "
        "{%0,%1,%2,%3}, {%4,%5,%6,%7}, {%8,%9}, {%0,%1,%2,%3};"
        : "+f"(d[0]), "+f"(d[1]), "+f"(d[2]), "+f"(d[3])
        : "r"(a[0]), "r"(a[1]), "r"(a[2]), "r"(a[3]), "r"(b[0]), "r"(b[1]));
}

__device__ __forceinline__ void ldsm4(uint32_t* r, uint32_t addr) {
    asm volatile("ldmatrix.sync.aligned.m8n8.x4.shared.b16 {%0,%1,%2,%3}, [%4];"
        : "=r"(r[0]), "=r"(r[1]), "=r"(r[2]), "=r"(r[3]) : "r"(addr));
}

__device__ __forceinline__ uint32_t pack_h2(float lo, float hi) {
    __half2 h = __floats2half2_rn(lo, hi);    // .x = lo, .y = hi
    return *reinterpret_cast<uint32_t*>(&h);
}

// =====================================================================
// transpose (fp32 in -> half out): out[C,R] = half(in[R,C]^T)
// =====================================================================
__global__ __launch_bounds__(256) void transpose_h_kernel(
    const float* __restrict__ in, __half* __restrict__ out, int R, int C)
{
    __shared__ float t[32][33];
    int c0 = blockIdx.x * 32, r0 = blockIdx.y * 32;
    int x = threadIdx.x, y = threadIdx.y;
    #pragma unroll
    for (int i = 0; i < 32; i += 8)
        t[y + i][x] = in[(size_t)(r0 + y + i) * C + c0 + x];
    __syncthreads();
    #pragma unroll
    for (int i = 0; i < 32; i += 8)
        out[(size_t)(c0 + y + i) * R + r0 + x] = __float2half(t[x][y + i]);
}

// batched 3-matrix transpose (Wq, Wk, Wv -> slices of g_wqkvt), each DD x DD
__global__ __launch_bounds__(256) void transpose3_h_kernel(
    const float* __restrict__ s0, const float* __restrict__ s1,
    const float* __restrict__ s2, __half* __restrict__ out)
{
    __shared__ float t[32][33];
    const float* in = (blockIdx.z == 0) ? s0 : (blockIdx.z == 1) ? s1 : s2;
    __half* o = out + (size_t)blockIdx.z * DD * DD;
    int c0 = blockIdx.x * 32, r0 = blockIdx.y * 32;
    int x = threadIdx.x, y = threadIdx.y;
    #pragma unroll
    for (int i = 0; i < 32; i += 8)
        t[y + i][x] = in[(size_t)(r0 + y + i) * DD + c0 + x];
    __syncthreads();
    #pragma unroll
    for (int i = 0; i < 32; i += 8)
        o[(size_t)(c0 + y + i) * DD + r0 + x] = __float2half(t[x][y + i]);
}

// =====================================================================
// LayerNorm: one block (256 thr) per row, D=768 = 3 elems/thread
// =====================================================================
__global__ __launch_bounds__(256) void layernorm_kernel(
    const float* __restrict__ x, const float* __restrict__ gamma,
    const float* __restrict__ beta, float* __restrict__ out)
{
    int row = blockIdx.x;
    int tid = threadIdx.x;
    const float* xr = x + (size_t)row * DD;

    float v0 = xr[tid], v1 = xr[tid + 256], v2 = xr[tid + 512];
    float s = v0 + v1 + v2;

    __shared__ float red[8];
    __shared__ float mu_s, rs_s;

    #pragma unroll
    for (int off = 16; off; off >>= 1) s += __shfl_xor_sync(0xffffffffu, s, off);
    if ((tid & 31) == 0) red[tid >> 5] = s;
    __syncthreads();
    if (tid == 0) {
        float t = 0.f;
        #pragma unroll
        for (int i = 0; i < 8; i++) t += red[i];
        mu_s = t * (1.0f / (float)DD);
    }
    __syncthreads();
    float mu = mu_s;
    float d0 = v0 - mu, d1 = v1 - mu, d2 = v2 - mu;
    float q = d0 * d0 + d1 * d1 + d2 * d2;
    #pragma unroll
    for (int off = 16; off; off >>= 1) q += __shfl_xor_sync(0xffffffffu, q, off);
    if ((tid & 31) == 0) red[tid >> 5] = q;
    __syncthreads();
    if (tid == 0) {
        float t = 0.f;
        #pragma unroll
        for (int i = 0; i < 8; i++) t += red[i];
        rs_s = rsqrtf(t * (1.0f / (float)DD) + EPSV);
    }
    __syncthreads();
    float rs = rs_s;
    float* orow = out + (size_t)row * DD;
    orow[tid]       = d0 * rs * gamma[tid]       + beta[tid];
    orow[tid + 256] = d1 * rs * gamma[tid + 256] + beta[tid + 256];
    orow[tid + 512] = d2 * rs * gamma[tid + 512] + beta[tid + 512];
}

// =====================================================================
// fp16 mma.sync GEMM with ldmatrix fragments
//   C[M,N] = alpha*A[M,K]@B + bias + relu + res
//   A: [M,K] row-major fp32 (converted to half in-kernel)
//   Bt: [N,K] row-major HALF (pre-transposed/converted)
//   block 128x128, K chunks of 32, double-buffered smem (1 sync/chunk),
//   8 warps (2x4) of 64x32 warp tiles, m16n8k16 fp16 mma, fp32 accum.
//   SMEM tiles: [128 rows][32 half] = rows of 4 x 16B chunks, XOR-swizzled
//   chunk' = chunk ^ ((row>>1)&3)  -> conflict-free STS.128 and ldmatrix.
// =====================================================================
template<bool BIAS, bool RELU, bool RES, bool QKVS>
__global__ __launch_bounds__(256, 2) void mma_gemm(
    int M, int N, int K, float alpha,
    const float* __restrict__ A, const __half* __restrict__ Bt,
    const float* __restrict__ bias, const float* __restrict__ res,
    float* __restrict__ C)
{
    __shared__ uint32_t As2[2][2048];   // 8KB per stage
    __shared__ uint32_t Bs2[2][2048];

    const int tid  = threadIdx.x;
    const int lane = tid & 31, wid = tid >> 5;
    const int g = lane >> 2, t4 = lane & 3;
    const int wm = wid & 1, wn = wid >> 1;       // warp grid 2 (m) x 4 (n)
    const int brow = blockIdx.y * 128;
    const int bcol = blockIdx.x * 128;

    // ---- staging geometry: thread handles (row = tid>>1, k-half = tid&1) ----
    const int sr  = tid >> 1;
    const int sks = tid & 1;
    const int ssw = (tid >> 2) & 3;              // (row>>1)&3
    const uint32_t aSt0 = 64u * sr + 16u * ((2 * sks + 0) ^ ssw);
    const uint32_t aSt1 = 64u * sr + 16u * ((2 * sks + 1) ^ ssw);
    const float*  Ag = A  + (size_t)(brow + sr) * K + sks * 16;
    const __half* Bg = Bt + (size_t)(bcol + sr) * K + sks * 16;

    // ---- ldmatrix per-lane geometry ----
    const int rA  = ((lane >> 3) & 1) * 8 + (lane & 7);
    const int cA  = lane >> 4;                   // 0/1 -> k chunk parity
    const int swA = (rA >> 1) & 3;
    const int rB  = ((lane >> 4) & 1) * 8 + (lane & 7);
    const int cB  = (lane >> 3) & 1;
    const int swB = (rB >> 1) & 3;

    const uint32_t aBase = smem_u32(As2) + 64u * rA;
    const uint32_t bBase = smem_u32(Bs2) + 64u * rB;

    float acc[4][4][4];
    #pragma unroll
    for (int mt = 0; mt < 4; mt++)
        #pragma unroll
        for (int nt = 0; nt < 4; nt++)
            #pragma unroll
            for (int r = 0; r < 4; r++) acc[mt][nt][r] = 0.f;

    const int nc = K >> 5;
    float4 va[4];
    uint4  vbu[2];

    char* smemA = (char*)As2;
    char* smemB = (char*)Bs2;

    // prologue: load + stage chunk 0
    #pragma unroll
    for (int i = 0; i < 4; i++) va[i] = *(const float4*)(Ag + i * 4);
    vbu[0] = *(const uint4*)(Bg);
    vbu[1] = *(const uint4*)(Bg + 8);
    {
        const float* af = (const float*)va;
        uint4 ua0, ua1;
        ua0.x = pack_h2(af[0], af[1]);  ua0.y = pack_h2(af[2], af[3]);
        ua0.z = pack_h2(af[4], af[5]);  ua0.w = pack_h2(af[6], af[7]);
        ua1.x = pack_h2(af[8], af[9]);  ua1.y = pack_h2(af[10], af[11]);
        ua1.z = pack_h2(af[12], af[13]); ua1.w = pack_h2(af[14], af[15]);
        *(uint4*)(smemA + aSt0) = ua0;
        *(uint4*)(smemA + aSt1) = ua1;
        *(uint4*)(smemB + aSt0) = vbu[0];
        *(uint4*)(smemB + aSt1) = vbu[1];
    }
    __syncthreads();

    for (int ch = 0; ch < nc; ch++) {
        const bool more = (ch + 1 < nc);
        const int s = ch & 1;
        if (more) {
            const int k0 = (ch + 1) << 5;
            #pragma unroll
            for (int i = 0; i < 4; i++) va[i] = *(const float4*)(Ag + k0 + i * 4);
            vbu[0] = *(const uint4*)(Bg + k0);
            vbu[1] = *(const uint4*)(Bg + k0 + 8);
        }

        // ---- MMA over the 32-K chunk from stage s (ldmatrix fragments) ----
        const uint32_t aS = aBase + (uint32_t)s * 8192u;
        const uint32_t bS = bBase + (uint32_t)s * 8192u;
        #pragma unroll
        for (int ks = 0; ks < 2; ks++) {
            uint32_t af[4][4], bf[2][4];
            const uint32_t aCh = 16u * (uint32_t)((2 * ks + cA) ^ swA);
            const uint32_t bCh = 16u * (uint32_t)((2 * ks + cB) ^ swB);
            #pragma unroll
            for (int mt = 0; mt < 4; mt++)
                ldsm4(af[mt], aS + 1024u * (uint32_t)(wm * 4 + mt) + aCh);
            #pragma unroll
            for (int jj = 0; jj < 2; jj++)
                ldsm4(bf[jj], bS + 1024u * (uint32_t)(wn * 2 + jj) + bCh);
            #pragma unroll
            for (int mt = 0; mt < 4; mt++)
                #pragma unroll
                for (int nt = 0; nt < 4; nt++)
                    mma16(acc[mt][nt], af[mt], &bf[nt >> 1][(nt & 1) * 2]);
        }

        if (more) {
            const float* af = (const float*)va;
            uint4 ua0, ua1;
            ua0.x = pack_h2(af[0], af[1]);  ua0.y = pack_h2(af[2], af[3]);
            ua0.z = pack_h2(af[4], af[5]);  ua0.w = pack_h2(af[6], af[7]);
            ua1.x = pack_h2(af[8], af[9]);  ua1.y = pack_h2(af[10], af[11]);
            ua1.z = pack_h2(af[12], af[13]); ua1.w = pack_h2(af[14], af[15]);
            char* An = smemA + (s ^ 1) * 8192;
            char* Bn = smemB + (s ^ 1) * 8192;
            *(uint4*)(An + aSt0) = ua0;
            *(uint4*)(An + aSt1) = ua1;
            *(uint4*)(Bn + aSt0) = vbu[0];
            *(uint4*)(Bn + aSt1) = vbu[1];
            __syncthreads();
        }
    }

    // ---- epilogue (fp32) ----
    const float aeff = QKVS ? ((bcol < DD) ? alpha : 1.0f) : alpha;
    #pragma unroll
    for (int mt = 0; mt < 4; mt++) {
        const int row0 = brow + wm * 64 + mt * 16 + g;
        const int row1 = row0 + 8;
        #pragma unroll
        for (int nt = 0; nt < 4; nt++) {
            const int col = bcol + wn * 32 + nt * 8 + t4 * 2;
            float2 lo, hi;
            lo.x = acc[mt][nt][0] * aeff; lo.y = acc[mt][nt][1] * aeff;
            hi.x = acc[mt][nt][2] * aeff; hi.y = acc[mt][nt][3] * aeff;
            if (BIAS) {
                const float2 bb = *(const float2*)&bias[col];
                lo.x += bb.x; lo.y += bb.y; hi.x += bb.x; hi.y += bb.y;
            }
            if (RELU) {
                lo.x = fmaxf(lo.x, 0.f); lo.y = fmaxf(lo.y, 0.f);
                hi.x = fmaxf(hi.x, 0.f); hi.y = fmaxf(hi.y, 0.f);
            }
            if (RES) {
                const float2 r0 = *(const float2*)&res[(size_t)row0 * N + col];
                const float2 r1 = *(const float2*)&res[(size_t)row1 * N + col];
                lo.x += r0.x; lo.y += r0.y; hi.x += r1.x; hi.y += r1.y;
            }
            *(float2*)&C[(size_t)row0 * N + col] = lo;
            *(float2*)&C[(size_t)row1 * N + col] = hi;
        }
    }
}

// =====================================================================
// BigBird flash attention (fp32)
//   grid (NB=64, H=12, B=2), 256 threads (8 warps), warp w owns rows w+8i.
//   q/k/v live in the fused QKV buffer: row stride QKVD.
// =====================================================================
struct PlanT { int v[(NBB - 2) * 8]; };

__global__ __launch_bounds__(256) void attn_kernel(
    const float* __restrict__ q, const float* __restrict__ k,
    const float* __restrict__ v, const PlanT plan,
    float* __restrict__ ctx)
{
    __shared__ float Qs[64 * 64];   // 16 KB
    __shared__ float Ks[32 * 68];   // padded: conflict-free lane-major reads
    __shared__ float Vs[32 * 64];
    __shared__ float Ps[64 * 33];   // padded P stage

    const int qb = blockIdx.x, h = blockIdx.y, b = blockIdx.z;
    const int tid = threadIdx.x;
    const int w = tid >> 5, lane = tid & 31;

    // load Q tile (pre-scaled by 1/sqrt(HD) in the fused QKV GEMM)
    const size_t qbase = ((size_t)(b * LL + qb * 64)) * QKVD + h * HDD;
    #pragma unroll
    for (int i = 0; i < 4; i++) {
        int f = tid + i * 256;        // 1024 float4s total
        int r = f >> 4, d4 = (f & 15) * 4;
        *(float4*)&Qs[r * 64 + d4] = *(const float4*)&q[qbase + (size_t)r * QKVD + d4];
    }

    float mreg[8], lreg[8], o0[8], o1[8];
    #pragma unroll
    for (int i = 0; i < 8; i++) { mreg[i] = -1e30f; lreg[i] = 0.f; o0[i] = 0.f; o1[i] = 0.f; }

    const int nkb = (qb == 0 || qb == NBB - 1) ? NBB : 8;

    for (int kbi = 0; kbi < nkb; kbi++) {
        int kb = (nkb == NBB) ? kbi : plan.v[(qb - 1) * 8 + kbi];
        for (int half = 0; half < 2; half++) {
            __syncthreads();   // protect Ks/Vs (and first-iter Qs) from prior consumers
            const size_t kbase = ((size_t)(b * LL + kb * 64 + half * 32)) * QKVD + h * HDD;
            #pragma unroll
            for (int i = 0; i < 2; i++) {
                int f = tid + i * 256;    // 512 float4s
                int c = f >> 4, d4 = (f & 15) * 4;
                *(float4*)&Ks[c * 68 + d4] = *(const float4*)&k[kbase + (size_t)c * QKVD + d4];
                *(float4*)&Vs[c * 64 + d4] = *(const float4*)&v[kbase + (size_t)c * QKVD + d4];
            }
            __syncthreads();

            // ---- QK^T + online softmax, one row at a time per warp ----
            #pragma unroll
            for (int i = 0; i < 8; i++) {
                int r = w + i * 8;
                const float4* qr = (const float4*)&Qs[r * 64];
                const float4* kr = (const float4*)&Ks[lane * 68];
                float s = 0.f;
                #pragma unroll
                for (int d4 = 0; d4 < 16; d4++) {
                    float4 a = qr[d4]; float4 bb = kr[d4];
                    s += a.x * bb.x + a.y * bb.y + a.z * bb.z + a.w * bb.w;
                }
                float cm = s;
                #pragma unroll
                for (int off = 16; off; off >>= 1)
                    cm = fmaxf(cm, __shfl_xor_sync(0xffffffffu, cm, off));
                float mn = fmaxf(mreg[i], cm);
                float sc = __expf(mreg[i] - mn);
                float p  = __expf(s - mn);
                float ps = p;
                #pragma unroll
                for (int off = 16; off; off >>= 1)
                    ps += __shfl_xor_sync(0xffffffffu, ps, off);
                lreg[i] = lreg[i] * sc + ps;
                mreg[i] = mn;
                o0[i] *= sc; o1[i] *= sc;
                Ps[r * 33 + lane] = p;
            }
            __syncwarp();

            // ---- P @ V: lane owns output dims (lane, lane+32), 2 rows at a time ----
            #pragma unroll
            for (int i = 0; i < 8; i += 2) {
                int r0 = w + i * 8, r1 = r0 + 8;
                float a0 = o0[i], a1 = o1[i], b0 = o0[i + 1], b1 = o1[i + 1];
                #pragma unroll
                for (int c = 0; c < 32; c++) {
                    float vv0 = Vs[c * 64 + lane];
                    float vv1 = Vs[c * 64 + lane + 32];
                    float p0 = Ps[r0 * 33 + c];
                    float p1 = Ps[r1 * 33 + c];
                    a0 += p0 * vv0; a1 += p0 * vv1;
                    b0 += p1 * vv0; b1 += p1 * vv1;
                }
                o0[i] = a0; o1[i] = a1; o0[i + 1] = b0; o1[i + 1] = b1;
            }
        }
    }

    // write context in [B*L, D] layout (col = h*64 + d) for the Wo GEMM
    const size_t obase = ((size_t)(b * LL + qb * 64)) * DD + h * HDD;
    #pragma unroll
    for (int i = 0; i < 8; i++) {
        int r = w + i * 8;
        float inv = 1.0f / lreg[i];
        ctx[obase + (size_t)r * DD + lane]      = o0[i] * inv;
        ctx[obase + (size_t)r * DD + lane + 32] = o1[i] * inv;
    }
}

// =====================================================================
// host-side numpy MT19937 (legacy RandomState(0)) -> BigBird plan
// =====================================================================
namespace hostmt {
struct MT {
    unsigned int key[624];
    int pos;
};
static void mt_seed(MT& s, unsigned int seed) {
    for (int p = 0; p < 624; p++) {
        s.key[p] = seed;
        seed = 1812433253u * (seed ^ (seed >> 30)) + (unsigned)p + 1u;
    }
    s.pos = 624;
}
static unsigned int mt_next(MT& s) {
    if (s.pos == 624) {
        for (int i = 0; i < 624; i++) {
            unsigned int y = (s.key[i] & 0x80000000u) | (s.key[(i + 1) % 624] & 0x7fffffffu);
            s.key[i] = s.key[(i + 397) % 624] ^ (y >> 1) ^ ((y & 1u) ? 0x9908b0dfu : 0u);
        }
        s.pos = 0;
    }
    unsigned int y = s.key[s.pos++];
    y ^= y >> 11;
    y ^= (y << 7)  & 0x9d2c5680u;
    y ^= (y << 15) & 0xefc60000u;
    y ^= y >> 18;
    return y;
}
static unsigned int mt_interval(MT& s, unsigned int mx) {
    if (mx == 0u) return 0u;
    unsigned int mask = mx;
    mask |= mask >> 1; mask |= mask >> 2; mask |= mask >> 4;
    mask |= mask >> 8; mask |= mask >> 16;
    unsigned int v;
    while ((v = (mt_next(s) & mask)) > mx) { }
    return v;
}
static void make_plan(int* plan) {
    MT st;
    mt_seed(st, 0u);
    for (int i = 1; i <= NBB - 2; i++) {
        int cand[64]; int n = 0;
        for (int j = 0; j < NBB; j++) {
            if (j == 0 || j == NBB - 1 || j == i - 1 || j == i || j == i + 1) continue;
            cand[n++] = j;
        }
        int perm[64];
        for (int j = 0; j < n; j++) perm[j] = j;
        for (int ii = n - 1; ii >= 1; ii--) {
            int j = (int)mt_interval(st, (unsigned)ii);
            int t = perm[ii]; perm[ii] = perm[j]; perm[j] = t;
        }
        int* row = plan + (i - 1) * 8;
        row[0] = 0; row[1] = NBB - 1; row[2] = i - 1; row[3] = i; row[4] = i + 1;
        for (int t = 0; t < 3; t++) row[5 + t] = cand[perm[t]];
    }
}
} // namespace hostmt

// =====================================================================
// launch
// =====================================================================
extern "C" void kernel_launch(void* const* d_in, const int* in_sizes, int n_in,
                              void* d_out, int out_size)
{
    (void)in_sizes; (void)n_in; (void)out_size;
    const float* x    = (const float*)d_in[0];
    const float* ln1s = (const float*)d_in[1];
    const float* ln1b = (const float*)d_in[2];
    const float* Wq   = (const float*)d_in[3];   // [D, H*HD] flat
    const float* Wk   = (const float*)d_in[4];
    const float* Wv   = (const float*)d_in[5];
    const float* Wo   = (const float*)d_in[6];   // [H*HD, D] flat
    const float* ln2s = (const float*)d_in[7];
    const float* ln2b = (const float*)d_in[8];
    const float* W1   = (const float*)d_in[9];   // [D, MLP]
    const float* b1   = (const float*)d_in[10];
    const float* W2   = (const float*)d_in[11];  // [MLP, D]
    const float* b2   = (const float*)d_in[12];
    float* out = (float*)d_out;

    void *ph, *pqkv, *pctx, *px1, *py, *pz;
    void *pwqkvt, *pwot, *pw1t, *pw2t;
    cudaGetSymbolAddress(&ph,    g_h);
    cudaGetSymbolAddress(&pqkv,  g_qkv);
    cudaGetSymbolAddress(&pctx,  g_ctx);
    cudaGetSymbolAddress(&px1,   g_x1);
    cudaGetSymbolAddress(&py,    g_y);
    cudaGetSymbolAddress(&pz,    g_z);
    cudaGetSymbolAddress(&pwqkvt, g_wqkvt);
    cudaGetSymbolAddress(&pwot,  g_wot);
    cudaGetSymbolAddress(&pw1t,  g_w1t);
    cudaGetSymbolAddress(&pw2t,  g_w2t);

    float*  fh    = (float*)ph;
    float*  fqkv  = (float*)pqkv;
    float*  fctx  = (float*)pctx;
    float*  fx1   = (float*)px1;
    float*  fy    = (float*)py;
    float*  fz    = (float*)pz;
    __half* wqkvt = (__half*)pwqkvt;
    __half* wot   = (__half*)pwot;
    __half* w1t   = (__half*)pw1t;
    __half* w2t   = (__half*)pw2t;

    // host-computed BigBird plan (numpy MT19937 replica) as kernel param
    PlanT plan;
    hostmt::make_plan(plan.v);

    dim3 tb(32, 8);

    // #1-#3 (ncu captures my 4th launch -> make it the QKV GEMM)
    transpose3_h_kernel<<<dim3(DD / 32, DD / 32, 3), tb>>>(Wq, Wk, Wv, wqkvt);
    transpose_h_kernel<<<dim3(DD / 32, DD / 32), tb>>>(Wo, wot, DD, DD);
    layernorm_kernel<<<ROWS, 256>>>(x, ln1s, ln1b, fh);

    // #4: fused QKV GEMM, N=2304, q-segment scaled by 0.125
    dim3 gqkv(QKVD / 128, ROWS / 128);
    mma_gemm<false, false, false, true><<<gqkv, 256>>>(ROWS, QKVD, DD, 0.125f, fh, wqkvt, nullptr, nullptr, fqkv);

    // remaining transposes (needed before the MLP GEMMs)
    transpose_h_kernel<<<dim3(MLPD / 32, DD / 32), tb>>>(W1, w1t, DD, MLPD);
    transpose_h_kernel<<<dim3(DD / 32, MLPD / 32), tb>>>(W2, w2t, MLPD, DD);

    // BigBird attention -> ctx [B*L, D]
    attn_kernel<<<dim3(NBB, HH, BB), 256>>>(fqkv, fqkv + DD, fqkv + 2 * DD, plan, fctx);

    // x1 = ctx @ Wo + x
    dim3 gdd(DD / 128, ROWS / 128);
    mma_gemm<false, false, true, false><<<gdd, 256>>>(ROWS, DD, DD, 1.0f, fctx, wot, nullptr, x, fx1);

    // y = LN2(x1)
    layernorm_kernel<<<ROWS, 256>>>(fx1, ln2s, ln2b, fy);

    // z = relu(y @ W1 + b1)
    dim3 gm1(MLPD / 128, ROWS / 128);
    mma_gemm<true, true, false, false><<<gm1, 256>>>(ROWS, MLPD, DD, 1.0f, fy, w1t, b1, nullptr, fz);

    // out = z @ W2 + b2 + x1
    mma_gemm<true, false, true, false><<<gdd, 256>>>(ROWS, DD, MLPD, 1.0f, fz, w2t, b2, fx1, out);
}